// round 9
// baseline (speedup 1.0000x reference)
#include <cuda_runtime.h>
#include <cuda_bf16.h>
#include <math.h>
#include <stdint.h>

// ---------------- problem constants ----------------
#define BB    2
#define SS    2048
#define DIM   2048
#define HH    16
#define NOPE  128
#define ROPE  64
#define QKHD  192
#define VHD   128
#define KVRANK 512
#define ROWS  (BB*SS)             // 4096
#define QCOLS (HH*QKHD)           // 3072
#define KVCOLS (KVRANK + HH*ROPE) // 1536

// ---------------- scratch (device globals) ----------------------------------
__device__ float g_q  [ROWS * QCOLS];
__device__ float g_kv [ROWS * KVCOLS];
__device__ float g_c  [ROWS * KVRANK];
__device__ float g_kn [ROWS * HH * NOPE];
__device__ float g_v  [ROWS * HH * VHD];
__device__ float g_K  [ROWS * HH * QKHD];
__device__ float g_O  [ROWS * HH * VHD];
// tf32-rounded x; transposed ([N][K]) + k-permuted tf32 weights
__device__ float g_xt   [ROWS * DIM];
__device__ float g_wqt  [QCOLS * DIM];
__device__ float g_wkvt [KVCOLS * DIM];
__device__ float g_wkt  [HH * NOPE * KVRANK];
__device__ float g_wvt  [HH * VHD * KVRANK];
__device__ float g_wot  [DIM * HH * VHD];

// ---------------- tf32 helpers ----------------------------------------------
__device__ __forceinline__ uint32_t f2tf32(float f) {
    uint32_t r;
    asm("cvt.rna.tf32.f32 %0, %1;" : "=r"(r) : "f"(f));
    return r;
}
__device__ __forceinline__ float f2tf32f(float f) {
    return __uint_as_float(f2tf32(f));
}
__device__ __forceinline__ void mma_tf32(float* d, const uint32_t* a, const uint32_t* b) {
    asm volatile(
        "mma.sync.aligned.m16n8k8.row.col.f32.tf32.tf32.f32 "
        "{%0,%1,%2,%3}, {%4,%5,%6,%7}, {%8,%9}, {%0,%1,%2,%3};"
        : "+f"(d[0]), "+f"(d[1]), "+f"(d[2]), "+f"(d[3])
        : "r"(a[0]), "r"(a[1]), "r"(a[2]), "r"(a[3]), "r"(b[0]), "r"(b[1]));
}

// ---------------- prep: tf32 round (plain layout, for activations) ----------
__global__ void tf32_convert_kernel(const float* __restrict__ src,
                                    float* __restrict__ dst, int n4)
{
    int i = blockIdx.x * blockDim.x + threadIdx.x;
    if (i >= n4) return;
    float4 v = *(const float4*)&src[i * 4];
    v.x = f2tf32f(v.x); v.y = f2tf32f(v.y);
    v.z = f2tf32f(v.z); v.w = f2tf32f(v.w);
    *(float4*)&dst[i * 4] = v;
}

// ---------------- prep: transpose+round+k-permute weights -------------------
// W[K][N] -> Wt[N][K], k' within each 32-block = (k&3)*8 + (k>>2).
__global__ void transpose_w_kernel(const float* __restrict__ W,
                                   float* __restrict__ Wt, int K, int N)
{
    __shared__ float t[32][33];
    const int kb0 = blockIdx.y * 32;
    const int nb0 = blockIdx.x * 32;
    const int tid = threadIdx.x;   // 256
    #pragma unroll
    for (int it = 0; it < 4; it++) {
        int kl = (tid >> 5) + it * 8;
        int nl = tid & 31;
        t[kl][nl] = W[(size_t)(kb0 + kl) * N + nb0 + nl];
    }
    __syncthreads();
    #pragma unroll
    for (int it = 0; it < 4; it++) {
        int nl = (tid >> 5) + it * 8;
        int kl = tid & 31;
        int kp = ((kl & 3) << 3) + (kl >> 2);
        Wt[(size_t)(nb0 + nl) * K + kb0 + kp] = f2tf32f(t[kl][nl]);
    }
}

// ---------------- tf32 tensor-core GEMM (512 threads, 32x32 warp tile) ------
// C[M][N] = Act[M][K] @ W + bias.  Wt = W^T [N][K] k-permuted; Act plain.
// 128x128x32 CTA tile, 16 warps in 4x4 grid, warp = 32m x 32n (acc 32 regs).
#define GBM 128
#define GBN 128
#define GBK 32
#define TPAD 36
#define TILE_STAGE (128 * TPAD)
#define GEMM_SMEM ((4 * TILE_STAGE) * sizeof(float))

__global__ __launch_bounds__(512, 2)
void gemm_tf32_kernel(const float* __restrict__ Wt, const float* __restrict__ Act,
                      const float* __restrict__ bias, float* __restrict__ C,
                      int M, int N, int K)
{
    extern __shared__ float sg[];
    float* As = sg;                    // [2][128 m][TPAD]  (plain k order)
    float* Ws = sg + 2 * TILE_STAGE;   // [2][128 n][TPAD]  (k-permuted)
    const uint32_t* Asu = (const uint32_t*)As;

    const int tid  = threadIdx.x;
    const int lane = tid & 31;
    const int warp = tid >> 5;         // 0..15
    const int g  = lane >> 2;
    const int tg = lane & 3;
    const int wm = warp & 3;           // m-offset wm*32
    const int wn = warp >> 2;          // n-offset wn*32
    const int row0 = blockIdx.y * GBM;
    const int col0 = blockIdx.x * GBN;

    const uint32_t as_base = (uint32_t)__cvta_generic_to_shared(As);
    const uint32_t ws_base = (uint32_t)__cvta_generic_to_shared(Ws);

    float acc[2][4][4];
    #pragma unroll
    for (int mt = 0; mt < 2; mt++)
        #pragma unroll
        for (int nt = 0; nt < 4; nt++)
            #pragma unroll
            for (int i = 0; i < 4; i++) acc[mt][nt][i] = 0.f;

    // staging: 512 threads, each 2 float4 for A + 2 for W
#define STAGE_LOAD(s_, kt_) do {                                               \
    _Pragma("unroll")                                                          \
    for (int n_ = 0; n_ < 2; n_++) {                                           \
        int i_ = tid + n_ * 512; int r_ = i_ >> 3; int c_ = (i_ & 7) * 4;      \
        uint32_t da_ = as_base + (uint32_t)(((s_) * TILE_STAGE + r_ * TPAD + c_) * 4); \
        asm volatile("cp.async.cg.shared.global [%0], [%1], 16;"               \
                     :: "r"(da_), "l"(Act + (size_t)(row0 + r_) * K + (kt_) * GBK + c_)); \
        uint32_t dw_ = ws_base + (uint32_t)(((s_) * TILE_STAGE + r_ * TPAD + c_) * 4); \
        asm volatile("cp.async.cg.shared.global [%0], [%1], 16;"               \
                     :: "r"(dw_), "l"(Wt + (size_t)(col0 + r_) * K + (kt_) * GBK + c_)); \
    }                                                                          \
    asm volatile("cp.async.commit_group;");                                    \
} while (0)

    const int KT = K / GBK;
    STAGE_LOAD(0, 0);

    for (int kt = 0; kt < KT; kt++) {
        const int s = kt & 1;
        if (kt + 1 < KT) {
            STAGE_LOAD(1 - s, kt + 1);
            asm volatile("cp.async.wait_group 1;");
        } else {
            asm volatile("cp.async.wait_group 0;");
        }
        __syncthreads();

        const uint32_t* Asl = Asu + s * TILE_STAGE;
        const float*    Wsl = Ws  + s * TILE_STAGE;

        #pragma unroll
        for (int hp = 0; hp < 2; hp++) {           // k-step pair {2hp, 2hp+1}
            uint32_t af[2][2][4];                   // [ksl][mt][4]
            #pragma unroll
            for (int ksl = 0; ksl < 2; ksl++) {
                const int kc = (hp * 2 + ksl) * 8 + tg;
                #pragma unroll
                for (int mt = 0; mt < 2; mt++) {
                    int row = wm * 32 + mt * 16 + g;
                    af[ksl][mt][0] = Asl[row * TPAD + kc];
                    af[ksl][mt][1] = Asl[(row + 8) * TPAD + kc];
                    af[ksl][mt][2] = Asl[row * TPAD + kc + 4];
                    af[ksl][mt][3] = Asl[(row + 8) * TPAD + kc + 4];
                }
            }
            #pragma unroll
            for (int nt = 0; nt < 4; nt++) {
                int col = wn * 32 + nt * 8 + g;
                float4 w = *(const float4*)&Wsl[col * TPAD + 8 * tg + 4 * hp];
                const uint32_t* wu = (const uint32_t*)&w;
                #pragma unroll
                for (int ksl = 0; ksl < 2; ksl++) {
                    uint32_t bf[2] = { wu[2 * ksl], wu[2 * ksl + 1] };
                    #pragma unroll
                    for (int mt = 0; mt < 2; mt++)
                        mma_tf32(acc[mt][nt], af[ksl][mt], bf);
                }
            }
        }
        __syncthreads();
    }
#undef STAGE_LOAD

    // epilogue: C[m][n] float2 along n
    #pragma unroll
    for (int mt = 0; mt < 2; mt++) {
        int r = row0 + wm * 32 + mt * 16 + g;
        #pragma unroll
        for (int nt = 0; nt < 4; nt++) {
            int c = col0 + wn * 32 + nt * 8 + tg * 2;
            float b0 = bias[c], b1 = bias[c + 1];
            float2 v0 = make_float2(acc[mt][nt][0] + b0, acc[mt][nt][1] + b1);
            float2 v1 = make_float2(acc[mt][nt][2] + b0, acc[mt][nt][3] + b1);
            *(float2*)&C[(size_t)r * N + c]       = v0;
            *(float2*)&C[(size_t)(r + 8) * N + c] = v1;
        }
    }
}

// ---------------- LayerNorm (tf32-rounded output, plain layout) -------------
__global__ void ln_kernel(const float* __restrict__ kv,
                          const float* __restrict__ gamma,
                          const float* __restrict__ beta,
                          float* __restrict__ out)
{
    const int row = blockIdx.x;
    const float* src = kv + (size_t)row * KVCOLS + HH * ROPE;
    float* dst = out + (size_t)row * KVRANK;
    const int tid = threadIdx.x;

    float v[4];
    float s = 0.f, s2 = 0.f;
    #pragma unroll
    for (int i = 0; i < 4; i++) {
        v[i] = src[tid + i * 128];
        s += v[i];
        s2 += v[i] * v[i];
    }
    __shared__ float rs[128], rs2[128];
    rs[tid] = s; rs2[tid] = s2;
    __syncthreads();
    for (int o = 64; o > 0; o >>= 1) {
        if (tid < o) { rs[tid] += rs[tid + o]; rs2[tid] += rs2[tid + o]; }
        __syncthreads();
    }
    float mean = rs[0] * (1.f / 512.f);
    float var  = rs2[0] * (1.f / 512.f) - mean * mean;
    float rstd = rsqrtf(var + 1e-5f);
    #pragma unroll
    for (int i = 0; i < 4; i++) {
        int c = tid + i * 128;
        dst[c] = f2tf32f((v[i] - mean) * rstd * gamma[c] + beta[c]);
    }
}

// ---------------- RoPE + K assembly (REFERENCE reshape semantics) -----------
__global__ void rope_assemble_kernel(float* __restrict__ q,
                                     const float* __restrict__ kv,
                                     const float* __restrict__ knope,
                                     const float* __restrict__ cosT,
                                     const float* __restrict__ sinT,
                                     float* __restrict__ Kout)
{
    int idx = blockIdx.x * blockDim.x + threadIdx.x;
    if (idx >= ROWS * HH * 32) return;
    int p   = idx & 31;
    int h   = (idx >> 5) & 15;
    int row = idx >> 9;
    int s   = row & (SS - 1);

    float cv = cosT[s * 32 + p];
    float sv = sinT[s * 32 + p];

    size_t qb = (size_t)row * QCOLS + h * QKHD + NOPE + 2 * p;
    float a = q[qb], b = q[qb + 1];
    q[qb]     = a * cv - b * sv;
    q[qb + 1] = a * sv + b * cv;

    const float* knr = knope + (size_t)row * (HH * NOPE);
    const float* krr = kv + (size_t)row * KVCOLS;
    size_t ko = ((size_t)row * HH + h) * QKHD;

    {
        int gg = h * QKHD + p * 4;
        float4 nv;
        if (gg < HH * NOPE) nv = *(const float4*)&knr[gg];
        else                nv = *(const float4*)&krr[gg - HH * NOPE];
        *(float4*)&Kout[ko + p * 4] = nv;
    }
    {
        int gg = h * QKHD + NOPE + 2 * p;
        float ka, kb;
        if (gg < HH * NOPE) { ka = knr[gg];              kb = knr[gg + 1]; }
        else                { ka = krr[gg - HH * NOPE];  kb = krr[gg - HH * NOPE + 1]; }
        Kout[ko + NOPE + 2 * p]     = ka * cv - kb * sv;
        Kout[ko + NOPE + 2 * p + 1] = ka * sv + kb * cv;
    }
}

// ---------------- tf32 tensor-core causal flash attention -------------------
#define ABQ 64
#define ABK 64
#define QSP 196
#define KSP 196
#define VSP 136
#define PSP 68
#define OSP 132
#define ATTN_SMEM ((ABQ*QSP + ABK*KSP + ABK*VSP + ABQ*PSP) * sizeof(float))

__global__ __launch_bounds__(256, 1)
void attn_mma_kernel(const float* __restrict__ Q,
                     const float* __restrict__ Kf,
                     const float* __restrict__ V,
                     float* __restrict__ O)
{
    const int q0 = blockIdx.x * ABQ;
    const int h  = blockIdx.y;
    const int b  = blockIdx.z;

    extern __shared__ float sm[];
    float* Qs = sm;
    float* Ks = Qs + ABQ * QSP;
    float* Vs = Ks + ABK * KSP;
    float* Ps = Vs + ABK * VSP;

    const int tid  = threadIdx.x;
    const int lane = tid & 31;
    const int wid  = tid >> 5;
    const int g    = lane >> 2;
    const int tg   = lane & 3;
    const int wq   = wid & 3;
    const int kh   = wid >> 2;
    const int rA   = wq * 16 + g;
    const float scale = 0.07216878364870322f;

    const float* Qg = Q + (((size_t)(b * SS + q0)) * HH + h) * QKHD;
    #pragma unroll
    for (int n = 0; n < 12; n++) {
        int i = tid + n * 256;
        int r = i / 48, d4 = (i % 48) * 4;
        float4 v = *(const float4*)&Qg[(size_t)r * (HH * QKHD) + d4];
        v.x = f2tf32f(v.x * scale); v.y = f2tf32f(v.y * scale);
        v.z = f2tf32f(v.z * scale); v.w = f2tf32f(v.w * scale);
        *(float4*)&Qs[r * QSP + d4] = v;
    }

    float m0 = -INFINITY, m1 = -INFINITY, l0 = 0.f, l1 = 0.f;
    float acc[16][4];
    #pragma unroll
    for (int nt = 0; nt < 16; nt++)
        #pragma unroll
        for (int i = 0; i < 4; i++) acc[nt][i] = 0.f;

    const int jend = blockIdx.x;
    for (int j = 0; j <= jend; j++) {
        const int k0 = j * ABK;
        __syncthreads();
        const float* Kg = Kf + (((size_t)(b * SS + k0)) * HH + h) * QKHD;
        #pragma unroll
        for (int n = 0; n < 12; n++) {
            int i = tid + n * 256;
            int r = i / 48, d4 = (i % 48) * 4;
            float4 v = *(const float4*)&Kg[(size_t)r * (HH * QKHD) + d4];
            v.x = f2tf32f(v.x); v.y = f2tf32f(v.y);
            v.z = f2tf32f(v.z); v.w = f2tf32f(v.w);
            *(float4*)&Ks[r * KSP + d4] = v;
        }
        const float* Vg = V + (((size_t)(b * SS + k0)) * HH + h) * VHD;
        #pragma unroll
        for (int n = 0; n < 8; n++) {
            int i = tid + n * 256;
            int r = i / 32, d4 = (i % 32) * 4;
            float4 v = *(const float4*)&Vg[(size_t)r * (HH * VHD) + d4];
            v.x = f2tf32f(v.x); v.y = f2tf32f(v.y);
            v.z = f2tf32f(v.z); v.w = f2tf32f(v.w);
            *(float4*)&Vs[r * VSP + d4] = v;
        }
        __syncthreads();

        float sc[4][4];
        #pragma unroll
        for (int nt = 0; nt < 4; nt++)
            #pragma unroll
            for (int i = 0; i < 4; i++) sc[nt][i] = 0.f;

        #pragma unroll
        for (int kc = 0; kc < 24; kc++) {
            uint32_t af[4];
            af[0] = __float_as_uint(Qs[rA * QSP + kc * 8 + tg]);
            af[1] = __float_as_uint(Qs[(rA + 8) * QSP + kc * 8 + tg]);
            af[2] = __float_as_uint(Qs[rA * QSP + kc * 8 + tg + 4]);
            af[3] = __float_as_uint(Qs[(rA + 8) * QSP + kc * 8 + tg + 4]);
            #pragma unroll
            for (int nt = 0; nt < 4; nt++) {
                int kvr = kh * 32 + nt * 8 + g;
                uint32_t bf[2];
                bf[0] = __float_as_uint(Ks[kvr * KSP + kc * 8 + tg]);
                bf[1] = __float_as_uint(Ks[kvr * KSP + kc * 8 + tg + 4]);
                mma_tf32(sc[nt], af, bf);
            }
        }

        if (j == jend) {
            #pragma unroll
            for (int nt = 0; nt < 4; nt++) {
                int colb = k0 + kh * 32 + nt * 8 + 2 * tg;
                int row0g = q0 + rA, row1g = q0 + rA + 8;
                if (colb     > row0g) sc[nt][0] = -INFINITY;
                if (colb + 1 > row0g) sc[nt][1] = -INFINITY;
                if (colb     > row1g) sc[nt][2] = -INFINITY;
                if (colb + 1 > row1g) sc[nt][3] = -INFINITY;
            }
        }

        float ml0 = -INFINITY, ml1 = -INFINITY;
        #pragma unroll
        for (int nt = 0; nt < 4; nt++) {
            ml0 = fmaxf(ml0, fmaxf(sc[nt][0], sc[nt][1]));
            ml1 = fmaxf(ml1, fmaxf(sc[nt][2], sc[nt][3]));
        }
        ml0 = fmaxf(ml0, __shfl_xor_sync(0xffffffffu, ml0, 1));
        ml0 = fmaxf(ml0, __shfl_xor_sync(0xffffffffu, ml0, 2));
        ml1 = fmaxf(ml1, __shfl_xor_sync(0xffffffffu, ml1, 1));
        ml1 = fmaxf(ml1, __shfl_xor_sync(0xffffffffu, ml1, 2));
        float mn0 = fmaxf(m0, ml0), mn1 = fmaxf(m1, ml1);
        float mr0 = (mn0 == -INFINITY) ? 0.f : mn0;
        float mr1 = (mn1 == -INFINITY) ? 0.f : mn1;
        float a0 = __expf(m0 - mr0);
        float a1 = __expf(m1 - mr1);

        float ll0 = 0.f, ll1 = 0.f;
        #pragma unroll
        for (int nt = 0; nt < 4; nt++) {
            float p0 = __expf(sc[nt][0] - mr0);
            float p1 = __expf(sc[nt][1] - mr0);
            float p2 = __expf(sc[nt][2] - mr1);
            float p3 = __expf(sc[nt][3] - mr1);
            ll0 += p0 + p1;
            ll1 += p2 + p3;
            int cb = kh * 32 + nt * 8 + 2 * tg;
            *(float2*)&Ps[rA * PSP + cb]       = make_float2(f2tf32f(p0), f2tf32f(p1));
            *(float2*)&Ps[(rA + 8) * PSP + cb] = make_float2(f2tf32f(p2), f2tf32f(p3));
        }
        ll0 += __shfl_xor_sync(0xffffffffu, ll0, 1);
        ll0 += __shfl_xor_sync(0xffffffffu, ll0, 2);
        ll1 += __shfl_xor_sync(0xffffffffu, ll1, 1);
        ll1 += __shfl_xor_sync(0xffffffffu, ll1, 2);

        m0 = mn0; m1 = mn1;
        l0 = l0 * a0 + ll0;
        l1 = l1 * a1 + ll1;

        #pragma unroll
        for (int nt = 0; nt < 16; nt++) {
            acc[nt][0] *= a0; acc[nt][1] *= a0;
            acc[nt][2] *= a1; acc[nt][3] *= a1;
        }
        __syncwarp();

        #pragma unroll
        for (int kc = 0; kc < 4; kc++) {
            uint32_t af[4];
            int pc = kh * 32 + kc * 8;
            af[0] = __float_as_uint(Ps[rA * PSP + pc + tg]);
            af[1] = __float_as_uint(Ps[(rA + 8) * PSP + pc + tg]);
            af[2] = __float_as_uint(Ps[rA * PSP + pc + tg + 4]);
            af[3] = __float_as_uint(Ps[(rA + 8) * PSP + pc + tg + 4]);
            int kv0 = kh * 32 + kc * 8 + tg;
            #pragma unroll
            for (int nt = 0; nt < 16; nt++) {
                uint32_t bf[2];
                bf[0] = __float_as_uint(Vs[kv0 * VSP + nt * 8 + g]);
                bf[1] = __float_as_uint(Vs[(kv0 + 4) * VSP + nt * 8 + g]);
                mma_tf32(acc[nt], af, bf);
            }
        }
        __syncwarp();
    }

    // ---- merge kv halves; write tf32-rounded O (plain layout) ----
    __syncthreads();
    float* Osh = Ks;
    float* msh = Ps;
    float* lsh = Ps + 64;

    if (kh == 1) {
        if (tg == 0) {
            msh[rA] = m0;  msh[rA + 8] = m1;
            lsh[rA] = l0;  lsh[rA + 8] = l1;
        }
        #pragma unroll
        for (int nt = 0; nt < 16; nt++) {
            int cb = nt * 8 + 2 * tg;
            *(float2*)&Osh[rA * OSP + cb]       = make_float2(acc[nt][0], acc[nt][1]);
            *(float2*)&Osh[(rA + 8) * OSP + cb] = make_float2(acc[nt][2], acc[nt][3]);
        }
    }
    __syncthreads();
    if (kh == 0) {
        float mB0 = msh[rA], mB1 = msh[rA + 8];
        float lB0 = lsh[rA], lB1 = lsh[rA + 8];
        float mm0 = fmaxf(m0, mB0), mm1 = fmaxf(m1, mB1);
        float wA0 = __expf(m0 - mm0),  wB0 = __expf(mB0 - mm0);
        float wA1 = __expf(m1 - mm1),  wB1 = __expf(mB1 - mm1);
        float inv0 = 1.f / (wA0 * l0 + wB0 * lB0);
        float inv1 = 1.f / (wA1 * l1 + wB1 * lB1);

        size_t ob0 = (((size_t)(b * SS + q0 + rA)) * HH + h) * VHD;
        size_t ob1 = (((size_t)(b * SS + q0 + rA + 8)) * HH + h) * VHD;
        #pragma unroll
        for (int nt = 0; nt < 16; nt++) {
            int cb = nt * 8 + 2 * tg;
            float2 oB0 = *(float2*)&Osh[rA * OSP + cb];
            float2 oB1 = *(float2*)&Osh[(rA + 8) * OSP + cb];
            float2 r0, r1;
            r0.x = f2tf32f((wA0 * acc[nt][0] + wB0 * oB0.x) * inv0);
            r0.y = f2tf32f((wA0 * acc[nt][1] + wB0 * oB0.y) * inv0);
            r1.x = f2tf32f((wA1 * acc[nt][2] + wB1 * oB1.x) * inv1);
            r1.y = f2tf32f((wA1 * acc[nt][3] + wB1 * oB1.y) * inv1);
            *(float2*)&O[ob0 + cb] = r0;
            *(float2*)&O[ob1 + cb] = r1;
        }
    }
}

// ---------------- launch -----------------------------------------------------
extern "C" void kernel_launch(void* const* d_in, const int* in_sizes, int n_in,
                              void* d_out, int out_size)
{
    const float* x       = (const float*)d_in[0];
    const float* wq_w    = (const float*)d_in[1];
    const float* wq_b    = (const float*)d_in[2];
    const float* wkv_a_w = (const float*)d_in[3];
    const float* wkv_a_b = (const float*)d_in[4];
    const float* kvn_g   = (const float*)d_in[5];
    const float* kvn_b   = (const float*)d_in[6];
    const float* wk_w    = (const float*)d_in[7];
    const float* wk_b    = (const float*)d_in[8];
    const float* wv_w    = (const float*)d_in[9];
    const float* wv_b    = (const float*)d_in[10];
    const float* wo_w    = (const float*)d_in[11];
    const float* wo_b    = (const float*)d_in[12];
    const float* cosT    = (const float*)d_in[13];
    const float* sinT    = (const float*)d_in[14];
    float* out = (float*)d_out;

    float *gq, *gkv, *gc, *gkn, *gv, *gK, *gO;
    float *xt, *wqt, *wkvt, *wkt, *wvt, *wot;
    cudaGetSymbolAddress((void**)&gq,   g_q);
    cudaGetSymbolAddress((void**)&gkv,  g_kv);
    cudaGetSymbolAddress((void**)&gc,   g_c);
    cudaGetSymbolAddress((void**)&gkn,  g_kn);
    cudaGetSymbolAddress((void**)&gv,   g_v);
    cudaGetSymbolAddress((void**)&gK,   g_K);
    cudaGetSymbolAddress((void**)&gO,   g_O);
    cudaGetSymbolAddress((void**)&xt,   g_xt);
    cudaGetSymbolAddress((void**)&wqt,  g_wqt);
    cudaGetSymbolAddress((void**)&wkvt, g_wkvt);
    cudaGetSymbolAddress((void**)&wkt,  g_wkt);
    cudaGetSymbolAddress((void**)&wvt,  g_wvt);
    cudaGetSymbolAddress((void**)&wot,  g_wot);

    cudaFuncSetAttribute(gemm_tf32_kernel, cudaFuncAttributeMaxDynamicSharedMemorySize, (int)GEMM_SMEM);
    cudaFuncSetAttribute(attn_mma_kernel, cudaFuncAttributeMaxDynamicSharedMemorySize, (int)ATTN_SMEM);

    // 0a) tf32-round x (plain layout)
    {
        int n4 = ROWS * DIM / 4;
        tf32_convert_kernel<<<(n4 + 255) / 256, 256>>>(x, xt, n4);
    }
    // 0b) transpose+round+permute weights  W[K][N] -> Wt[N][K]
    transpose_w_kernel<<<dim3(QCOLS/32,  DIM/32),    256>>>(wq_w,    wqt,  DIM,    QCOLS);
    transpose_w_kernel<<<dim3(KVCOLS/32, DIM/32),    256>>>(wkv_a_w, wkvt, DIM,    KVCOLS);
    transpose_w_kernel<<<dim3((HH*NOPE)/32, KVRANK/32), 256>>>(wk_w, wkt,  KVRANK, HH*NOPE);
    transpose_w_kernel<<<dim3((HH*VHD)/32,  KVRANK/32), 256>>>(wv_w, wvt,  KVRANK, HH*VHD);
    transpose_w_kernel<<<dim3(DIM/32, (HH*VHD)/32),  256>>>(wo_w,    wot,  HH*VHD, DIM);

    // 1) q = x @ wq_w + b
    gemm_tf32_kernel<<<dim3(QCOLS/GBN, ROWS/GBM), 512, GEMM_SMEM>>>(wqt, xt, wq_b, gq, ROWS, QCOLS, DIM);
    // 2) kv = x @ wkv_a_w + b
    gemm_tf32_kernel<<<dim3(KVCOLS/GBN, ROWS/GBM), 512, GEMM_SMEM>>>(wkvt, xt, wkv_a_b, gkv, ROWS, KVCOLS, DIM);
    // 3) layernorm (tf32 output)
    ln_kernel<<<ROWS, 128>>>(gkv, kvn_g, kvn_b, gc);
    // 4) k_nope = c @ wk_w + b
    gemm_tf32_kernel<<<dim3((HH*NOPE)/GBN, ROWS/GBM), 512, GEMM_SMEM>>>(wkt, gc, wk_b, gkn, ROWS, HH*NOPE, KVRANK);
    // 5) v = c @ wv_w + b
    gemm_tf32_kernel<<<dim3((HH*VHD)/GBN, ROWS/GBM), 512, GEMM_SMEM>>>(wvt, gc, wv_b, gv, ROWS, HH*VHD, KVRANK);
    // 6) rope + assemble K
    {
        int total = ROWS * HH * 32;
        rope_assemble_kernel<<<(total + 255) / 256, 256>>>(gq, gkv, gkn, cosT, sinT, gK);
    }
    // 7) attention (tf32 mma)
    attn_mma_kernel<<<dim3(SS/ABQ, HH, BB), 256, ATTN_SMEM>>>(gq, gK, gv, gO);
    // 8) out = O @ wo_w + b
    gemm_tf32_kernel<<<dim3(DIM/GBN, ROWS/GBM), 512, GEMM_SMEM>>>(wot, gO, wo_b, out, ROWS, DIM, HH*VHD);
}

// round 11
// speedup vs baseline: 1.4112x; 1.4112x over previous
#include <cuda_runtime.h>
#include <cuda_fp16.h>
#include <cuda_bf16.h>
#include <math.h>
#include <stdint.h>

// ---------------- problem constants ----------------
#define BB    2
#define SS    2048
#define DIM   2048
#define HH    16
#define NOPE  128
#define ROPE  64
#define QKHD  192
#define VHD   128
#define KVRANK 512
#define ROWS  (BB*SS)             // 4096
#define QCOLS (HH*QKHD)           // 3072
#define KVCOLS (KVRANK + HH*ROPE) // 1536

// ---------------- scratch (device globals) ----------------------------------
__device__ float  g_q  [ROWS * QCOLS];
__device__ float  g_kv [ROWS * KVCOLS];
__device__ __half g_c  [ROWS * KVRANK];     // fp16 latent (GEMM Act input)
__device__ float  g_kn [ROWS * HH * NOPE];
__device__ float  g_v  [ROWS * HH * VHD];
__device__ float  g_K  [ROWS * HH * QKHD];
__device__ __half g_O  [ROWS * HH * VHD];   // fp16 attention out (GEMM Act input)
// fp16 x; transposed ([N][K]) fp16 weights
__device__ __half g_xt   [ROWS * DIM];
__device__ __half g_wqt  [QCOLS * DIM];
__device__ __half g_wkvt [KVCOLS * DIM];
__device__ __half g_wkt  [HH * NOPE * KVRANK];
__device__ __half g_wvt  [HH * VHD * KVRANK];
__device__ __half g_wot  [DIM * HH * VHD];

// ---------------- helpers -----------------------------------------------------
__device__ __forceinline__ uint32_t f2tf32(float f) {
    uint32_t r;
    asm("cvt.rna.tf32.f32 %0, %1;" : "=r"(r) : "f"(f));
    return r;
}
__device__ __forceinline__ float f2tf32f(float f) {
    return __uint_as_float(f2tf32(f));
}
__device__ __forceinline__ void mma_tf32(float* d, const uint32_t* a, const uint32_t* b) {
    asm volatile(
        "mma.sync.aligned.m16n8k8.row.col.f32.tf32.tf32.f32 "
        "{%0,%1,%2,%3}, {%4,%5,%6,%7}, {%8,%9}, {%0,%1,%2,%3};"
        : "+f"(d[0]), "+f"(d[1]), "+f"(d[2]), "+f"(d[3])
        : "r"(a[0]), "r"(a[1]), "r"(a[2]), "r"(a[3]), "r"(b[0]), "r"(b[1]));
}
__device__ __forceinline__ void mma_f16(float* d, const uint32_t* a, const uint32_t* b) {
    asm volatile(
        "mma.sync.aligned.m16n8k16.row.col.f32.f16.f16.f32 "
        "{%0,%1,%2,%3}, {%4,%5,%6,%7}, {%8,%9}, {%0,%1,%2,%3};"
        : "+f"(d[0]), "+f"(d[1]), "+f"(d[2]), "+f"(d[3])
        : "r"(a[0]), "r"(a[1]), "r"(a[2]), "r"(a[3]), "r"(b[0]), "r"(b[1]));
}

// ---------------- prep: fp32 -> fp16 (plain layout, activations) ------------
__global__ void f2h_kernel(const float* __restrict__ src,
                           __half* __restrict__ dst, int n4)
{
    int i = blockIdx.x * blockDim.x + threadIdx.x;
    if (i >= n4) return;
    float4 v = *(const float4*)&src[i * 4];
    __half2 h0 = __floats2half2_rn(v.x, v.y);
    __half2 h1 = __floats2half2_rn(v.z, v.w);
    *(__half2*)&dst[i * 4]     = h0;
    *(__half2*)&dst[i * 4 + 2] = h1;
}

// ---------------- prep: transpose+round weights (W[K][N] -> Wt[N][K] fp16) --
__global__ void transpose_w_kernel(const float* __restrict__ W,
                                   __half* __restrict__ Wt, int K, int N)
{
    __shared__ float t[32][33];
    const int kb0 = blockIdx.y * 32;
    const int nb0 = blockIdx.x * 32;
    const int tid = threadIdx.x;   // 256
    #pragma unroll
    for (int it = 0; it < 4; it++) {
        int kl = (tid >> 5) + it * 8;
        int nl = tid & 31;
        t[kl][nl] = W[(size_t)(kb0 + kl) * N + nb0 + nl];
    }
    __syncthreads();
    #pragma unroll
    for (int it = 0; it < 4; it++) {
        int nl = (tid >> 5) + it * 8;
        int kl = tid & 31;
        Wt[(size_t)(nb0 + nl) * K + kb0 + kl] = __float2half(t[kl][nl]);
    }
}

// ---------------- fp16 tensor-core GEMM -------------------------------------
// C[M][N] = Act[M][K] @ W + bias.  Wt = W^T [N][K] fp16; Act fp16.
// 128x128x32 CTA tile, 256 threads (8 warps, 4x2), warp = 32m x 64n,
// mma.sync.m16n8k16.f16, double-buffered cp.async staging.
#define GBM 128
#define GBN 128
#define GBK 32
#define TPAD 40                      // halves per smem row (80B, 16B-mult)
#define TILE_STAGE (128 * TPAD)      // halves
#define GEMM_SMEM ((4 * TILE_STAGE) * sizeof(__half))

__global__ __launch_bounds__(256, 2)
void gemm_f16_kernel(const __half* __restrict__ Wt, const __half* __restrict__ Act,
                     const float* __restrict__ bias, float* __restrict__ C,
                     int M, int N, int K)
{
    extern __shared__ __half sh[];
    __half* As = sh;                    // [2][128 m][TPAD]
    __half* Ws = sh + 2 * TILE_STAGE;   // [2][128 n][TPAD]

    const int tid  = threadIdx.x;
    const int lane = tid & 31;
    const int warp = tid >> 5;
    const int g  = lane >> 2;
    const int tg = lane & 3;
    const int wm = warp & 3;           // warp m-offset wm*32
    const int wn = warp >> 2;          // warp n-offset wn*64
    const int row0 = blockIdx.y * GBM;
    const int col0 = blockIdx.x * GBN;

    const uint32_t as_base = (uint32_t)__cvta_generic_to_shared(As);
    const uint32_t ws_base = (uint32_t)__cvta_generic_to_shared(Ws);

    float acc[2][8][4];
    #pragma unroll
    for (int mt = 0; mt < 2; mt++)
        #pragma unroll
        for (int nt = 0; nt < 8; nt++)
            #pragma unroll
            for (int i = 0; i < 4; i++) acc[mt][nt][i] = 0.f;

    // staging: per tile 128 rows x 64B = 512 x 16B chunks; A+B = 1024; 4/thread
#define STAGE_LOAD(s_, kt_) do {                                               \
    _Pragma("unroll")                                                          \
    for (int n_ = 0; n_ < 2; n_++) {                                           \
        int i_ = tid + n_ * 256; int r_ = i_ >> 2; int c_ = (i_ & 3) * 8;      \
        uint32_t da_ = as_base + (uint32_t)(((s_) * TILE_STAGE + r_ * TPAD + c_) * 2); \
        asm volatile("cp.async.cg.shared.global [%0], [%1], 16;"               \
                     :: "r"(da_), "l"(Act + (size_t)(row0 + r_) * K + (kt_) * GBK + c_)); \
        uint32_t dw_ = ws_base + (uint32_t)(((s_) * TILE_STAGE + r_ * TPAD + c_) * 2); \
        asm volatile("cp.async.cg.shared.global [%0], [%1], 16;"               \
                     :: "r"(dw_), "l"(Wt + (size_t)(col0 + r_) * K + (kt_) * GBK + c_)); \
    }                                                                          \
    asm volatile("cp.async.commit_group;");                                    \
} while (0)

    const int KT = K / GBK;
    STAGE_LOAD(0, 0);

    for (int kt = 0; kt < KT; kt++) {
        const int s = kt & 1;
        if (kt + 1 < KT) {
            STAGE_LOAD(1 - s, kt + 1);
            asm volatile("cp.async.wait_group 1;");
        } else {
            asm volatile("cp.async.wait_group 0;");
        }
        __syncthreads();

        const __half* Asl = As + s * TILE_STAGE;
        const __half* Wsl = Ws + s * TILE_STAGE;

        #pragma unroll
        for (int ks = 0; ks < 2; ks++) {           // two m16n8k16 steps
            const int kk = ks * 16 + 2 * tg;
            uint32_t af[2][4];
            #pragma unroll
            for (int mt = 0; mt < 2; mt++) {
                int row = wm * 32 + mt * 16 + g;
                af[mt][0] = *(const uint32_t*)&Asl[row * TPAD + kk];
                af[mt][1] = *(const uint32_t*)&Asl[(row + 8) * TPAD + kk];
                af[mt][2] = *(const uint32_t*)&Asl[row * TPAD + kk + 8];
                af[mt][3] = *(const uint32_t*)&Asl[(row + 8) * TPAD + kk + 8];
            }
            #pragma unroll
            for (int nt = 0; nt < 8; nt++) {
                int col = wn * 64 + nt * 8 + g;
                uint32_t bf[2];
                bf[0] = *(const uint32_t*)&Wsl[col * TPAD + kk];
                bf[1] = *(const uint32_t*)&Wsl[col * TPAD + kk + 8];
                #pragma unroll
                for (int mt = 0; mt < 2; mt++)
                    mma_f16(acc[mt][nt], af[mt], bf);
            }
        }
        __syncthreads();
    }
#undef STAGE_LOAD

    // epilogue: C[m][n] float2 along n (R8-proven pattern)
    #pragma unroll
    for (int mt = 0; mt < 2; mt++) {
        int r = row0 + wm * 32 + mt * 16 + g;
        #pragma unroll
        for (int nt = 0; nt < 8; nt++) {
            int c = col0 + wn * 64 + nt * 8 + tg * 2;
            float b0 = bias[c], b1 = bias[c + 1];
            float2 v0 = make_float2(acc[mt][nt][0] + b0, acc[mt][nt][1] + b1);
            float2 v1 = make_float2(acc[mt][nt][2] + b0, acc[mt][nt][3] + b1);
            *(float2*)&C[(size_t)r * N + c]       = v0;
            *(float2*)&C[(size_t)(r + 8) * N + c] = v1;
        }
    }
}

// ---------------- LayerNorm (fp16 output, plain layout) ---------------------
__global__ void ln_kernel(const float* __restrict__ kv,
                          const float* __restrict__ gamma,
                          const float* __restrict__ beta,
                          __half* __restrict__ out)
{
    const int row = blockIdx.x;
    const float* src = kv + (size_t)row * KVCOLS + HH * ROPE;
    __half* dst = out + (size_t)row * KVRANK;
    const int tid = threadIdx.x;

    float v[4];
    float s = 0.f, s2 = 0.f;
    #pragma unroll
    for (int i = 0; i < 4; i++) {
        v[i] = src[tid + i * 128];
        s += v[i];
        s2 += v[i] * v[i];
    }
    __shared__ float rs[128], rs2[128];
    rs[tid] = s; rs2[tid] = s2;
    __syncthreads();
    for (int o = 64; o > 0; o >>= 1) {
        if (tid < o) { rs[tid] += rs[tid + o]; rs2[tid] += rs2[tid + o]; }
        __syncthreads();
    }
    float mean = rs[0] * (1.f / 512.f);
    float var  = rs2[0] * (1.f / 512.f) - mean * mean;
    float rstd = rsqrtf(var + 1e-5f);
    #pragma unroll
    for (int i = 0; i < 4; i++) {
        int c = tid + i * 128;
        dst[c] = __float2half((v[i] - mean) * rstd * gamma[c] + beta[c]);
    }
}

// ---------------- RoPE + K assembly (REFERENCE reshape semantics) -----------
__global__ void rope_assemble_kernel(float* __restrict__ q,
                                     const float* __restrict__ kv,
                                     const float* __restrict__ knope,
                                     const float* __restrict__ cosT,
                                     const float* __restrict__ sinT,
                                     float* __restrict__ Kout)
{
    int idx = blockIdx.x * blockDim.x + threadIdx.x;
    if (idx >= ROWS * HH * 32) return;
    int p   = idx & 31;
    int h   = (idx >> 5) & 15;
    int row = idx >> 9;
    int s   = row & (SS - 1);

    float cv = cosT[s * 32 + p];
    float sv = sinT[s * 32 + p];

    size_t qb = (size_t)row * QCOLS + h * QKHD + NOPE + 2 * p;
    float a = q[qb], b = q[qb + 1];
    q[qb]     = a * cv - b * sv;
    q[qb + 1] = a * sv + b * cv;

    const float* knr = knope + (size_t)row * (HH * NOPE);
    const float* krr = kv + (size_t)row * KVCOLS;
    size_t ko = ((size_t)row * HH + h) * QKHD;

    {
        int gg = h * QKHD + p * 4;
        float4 nv;
        if (gg < HH * NOPE) nv = *(const float4*)&knr[gg];
        else                nv = *(const float4*)&krr[gg - HH * NOPE];
        *(float4*)&Kout[ko + p * 4] = nv;
    }
    {
        int gg = h * QKHD + NOPE + 2 * p;
        float ka, kb;
        if (gg < HH * NOPE) { ka = knr[gg];              kb = knr[gg + 1]; }
        else                { ka = krr[gg - HH * NOPE];  kb = krr[gg - HH * NOPE + 1]; }
        Kout[ko + NOPE + 2 * p]     = ka * cv - kb * sv;
        Kout[ko + NOPE + 2 * p + 1] = ka * sv + kb * cv;
    }
}

// ---------------- tf32 tensor-core causal flash attention (R8 best) ---------
// Only change vs R8: O is written as fp16 (feeds the fp16 o-proj GEMM).
#define ABQ 64
#define ABK 64
#define QSP 196
#define KSP 196
#define VSP 136
#define PSP 68
#define OSP 132
#define ATTN_SMEM ((ABQ*QSP + ABK*KSP + ABK*VSP + ABQ*PSP) * sizeof(float))

__global__ __launch_bounds__(256, 1)
void attn_mma_kernel(const float* __restrict__ Q,
                     const float* __restrict__ Kf,
                     const float* __restrict__ V,
                     __half* __restrict__ O)
{
    const int q0 = blockIdx.x * ABQ;
    const int h  = blockIdx.y;
    const int b  = blockIdx.z;

    extern __shared__ float sm[];
    float* Qs = sm;
    float* Ks = Qs + ABQ * QSP;
    float* Vs = Ks + ABK * KSP;
    float* Ps = Vs + ABK * VSP;

    const int tid  = threadIdx.x;
    const int lane = tid & 31;
    const int wid  = tid >> 5;
    const int g    = lane >> 2;
    const int tg   = lane & 3;
    const int wq   = wid & 3;
    const int kh   = wid >> 2;
    const int rA   = wq * 16 + g;
    const float scale = 0.07216878364870322f;

    const float* Qg = Q + (((size_t)(b * SS + q0)) * HH + h) * QKHD;
    #pragma unroll
    for (int n = 0; n < 12; n++) {
        int i = tid + n * 256;
        int r = i / 48, d4 = (i % 48) * 4;
        float4 v = *(const float4*)&Qg[(size_t)r * (HH * QKHD) + d4];
        v.x = f2tf32f(v.x * scale); v.y = f2tf32f(v.y * scale);
        v.z = f2tf32f(v.z * scale); v.w = f2tf32f(v.w * scale);
        *(float4*)&Qs[r * QSP + d4] = v;
    }

    float m0 = -INFINITY, m1 = -INFINITY, l0 = 0.f, l1 = 0.f;
    float acc[16][4];
    #pragma unroll
    for (int nt = 0; nt < 16; nt++)
        #pragma unroll
        for (int i = 0; i < 4; i++) acc[nt][i] = 0.f;

    const int jend = blockIdx.x;
    for (int j = 0; j <= jend; j++) {
        const int k0 = j * ABK;
        __syncthreads();
        const float* Kg = Kf + (((size_t)(b * SS + k0)) * HH + h) * QKHD;
        #pragma unroll
        for (int n = 0; n < 12; n++) {
            int i = tid + n * 256;
            int r = i / 48, d4 = (i % 48) * 4;
            float4 v = *(const float4*)&Kg[(size_t)r * (HH * QKHD) + d4];
            v.x = f2tf32f(v.x); v.y = f2tf32f(v.y);
            v.z = f2tf32f(v.z); v.w = f2tf32f(v.w);
            *(float4*)&Ks[r * KSP + d4] = v;
        }
        const float* Vg = V + (((size_t)(b * SS + k0)) * HH + h) * VHD;
        #pragma unroll
        for (int n = 0; n < 8; n++) {
            int i = tid + n * 256;
            int r = i / 32, d4 = (i % 32) * 4;
            float4 v = *(const float4*)&Vg[(size_t)r * (HH * VHD) + d4];
            v.x = f2tf32f(v.x); v.y = f2tf32f(v.y);
            v.z = f2tf32f(v.z); v.w = f2tf32f(v.w);
            *(float4*)&Vs[r * VSP + d4] = v;
        }
        __syncthreads();

        float sc[4][4];
        #pragma unroll
        for (int nt = 0; nt < 4; nt++)
            #pragma unroll
            for (int i = 0; i < 4; i++) sc[nt][i] = 0.f;

        #pragma unroll
        for (int kc = 0; kc < 24; kc++) {
            uint32_t af[4];
            af[0] = __float_as_uint(Qs[rA * QSP + kc * 8 + tg]);
            af[1] = __float_as_uint(Qs[(rA + 8) * QSP + kc * 8 + tg]);
            af[2] = __float_as_uint(Qs[rA * QSP + kc * 8 + tg + 4]);
            af[3] = __float_as_uint(Qs[(rA + 8) * QSP + kc * 8 + tg + 4]);
            #pragma unroll
            for (int nt = 0; nt < 4; nt++) {
                int kvr = kh * 32 + nt * 8 + g;
                uint32_t bf[2];
                bf[0] = __float_as_uint(Ks[kvr * KSP + kc * 8 + tg]);
                bf[1] = __float_as_uint(Ks[kvr * KSP + kc * 8 + tg + 4]);
                mma_tf32(sc[nt], af, bf);
            }
        }

        if (j == jend) {
            #pragma unroll
            for (int nt = 0; nt < 4; nt++) {
                int colb = k0 + kh * 32 + nt * 8 + 2 * tg;
                int row0g = q0 + rA, row1g = q0 + rA + 8;
                if (colb     > row0g) sc[nt][0] = -INFINITY;
                if (colb + 1 > row0g) sc[nt][1] = -INFINITY;
                if (colb     > row1g) sc[nt][2] = -INFINITY;
                if (colb + 1 > row1g) sc[nt][3] = -INFINITY;
            }
        }

        float ml0 = -INFINITY, ml1 = -INFINITY;
        #pragma unroll
        for (int nt = 0; nt < 4; nt++) {
            ml0 = fmaxf(ml0, fmaxf(sc[nt][0], sc[nt][1]));
            ml1 = fmaxf(ml1, fmaxf(sc[nt][2], sc[nt][3]));
        }
        ml0 = fmaxf(ml0, __shfl_xor_sync(0xffffffffu, ml0, 1));
        ml0 = fmaxf(ml0, __shfl_xor_sync(0xffffffffu, ml0, 2));
        ml1 = fmaxf(ml1, __shfl_xor_sync(0xffffffffu, ml1, 1));
        ml1 = fmaxf(ml1, __shfl_xor_sync(0xffffffffu, ml1, 2));
        float mn0 = fmaxf(m0, ml0), mn1 = fmaxf(m1, ml1);
        float mr0 = (mn0 == -INFINITY) ? 0.f : mn0;
        float mr1 = (mn1 == -INFINITY) ? 0.f : mn1;
        float a0 = __expf(m0 - mr0);
        float a1 = __expf(m1 - mr1);

        float ll0 = 0.f, ll1 = 0.f;
        #pragma unroll
        for (int nt = 0; nt < 4; nt++) {
            float p0 = __expf(sc[nt][0] - mr0);
            float p1 = __expf(sc[nt][1] - mr0);
            float p2 = __expf(sc[nt][2] - mr1);
            float p3 = __expf(sc[nt][3] - mr1);
            ll0 += p0 + p1;
            ll1 += p2 + p3;
            int cb = kh * 32 + nt * 8 + 2 * tg;
            *(float2*)&Ps[rA * PSP + cb]       = make_float2(f2tf32f(p0), f2tf32f(p1));
            *(float2*)&Ps[(rA + 8) * PSP + cb] = make_float2(f2tf32f(p2), f2tf32f(p3));
        }
        ll0 += __shfl_xor_sync(0xffffffffu, ll0, 1);
        ll0 += __shfl_xor_sync(0xffffffffu, ll0, 2);
        ll1 += __shfl_xor_sync(0xffffffffu, ll1, 1);
        ll1 += __shfl_xor_sync(0xffffffffu, ll1, 2);

        m0 = mn0; m1 = mn1;
        l0 = l0 * a0 + ll0;
        l1 = l1 * a1 + ll1;

        #pragma unroll
        for (int nt = 0; nt < 16; nt++) {
            acc[nt][0] *= a0; acc[nt][1] *= a0;
            acc[nt][2] *= a1; acc[nt][3] *= a1;
        }
        __syncwarp();

        #pragma unroll
        for (int kc = 0; kc < 4; kc++) {
            uint32_t af[4];
            int pc = kh * 32 + kc * 8;
            af[0] = __float_as_uint(Ps[rA * PSP + pc + tg]);
            af[1] = __float_as_uint(Ps[(rA + 8) * PSP + pc + tg]);
            af[2] = __float_as_uint(Ps[rA * PSP + pc + tg + 4]);
            af[3] = __float_as_uint(Ps[(rA + 8) * PSP + pc + tg + 4]);
            int kv0 = kh * 32 + kc * 8 + tg;
            #pragma unroll
            for (int nt = 0; nt < 16; nt++) {
                uint32_t bf[2];
                bf[0] = __float_as_uint(Vs[kv0 * VSP + nt * 8 + g]);
                bf[1] = __float_as_uint(Vs[(kv0 + 4) * VSP + nt * 8 + g]);
                mma_tf32(acc[nt], af, bf);
            }
        }
        __syncwarp();
    }

    // ---- merge kv halves; write fp16 O (plain layout) ----
    __syncthreads();
    float* Osh = Ks;
    float* msh = Ps;
    float* lsh = Ps + 64;

    if (kh == 1) {
        if (tg == 0) {
            msh[rA] = m0;  msh[rA + 8] = m1;
            lsh[rA] = l0;  lsh[rA + 8] = l1;
        }
        #pragma unroll
        for (int nt = 0; nt < 16; nt++) {
            int cb = nt * 8 + 2 * tg;
            *(float2*)&Osh[rA * OSP + cb]       = make_float2(acc[nt][0], acc[nt][1]);
            *(float2*)&Osh[(rA + 8) * OSP + cb] = make_float2(acc[nt][2], acc[nt][3]);
        }
    }
    __syncthreads();
    if (kh == 0) {
        float mB0 = msh[rA], mB1 = msh[rA + 8];
        float lB0 = lsh[rA], lB1 = lsh[rA + 8];
        float mm0 = fmaxf(m0, mB0), mm1 = fmaxf(m1, mB1);
        float wA0 = __expf(m0 - mm0),  wB0 = __expf(mB0 - mm0);
        float wA1 = __expf(m1 - mm1),  wB1 = __expf(mB1 - mm1);
        float inv0 = 1.f / (wA0 * l0 + wB0 * lB0);
        float inv1 = 1.f / (wA1 * l1 + wB1 * lB1);

        size_t ob0 = (((size_t)(b * SS + q0 + rA)) * HH + h) * VHD;
        size_t ob1 = (((size_t)(b * SS + q0 + rA + 8)) * HH + h) * VHD;
        #pragma unroll
        for (int nt = 0; nt < 16; nt++) {
            int cb = nt * 8 + 2 * tg;
            float2 oB0 = *(float2*)&Osh[rA * OSP + cb];
            float2 oB1 = *(float2*)&Osh[(rA + 8) * OSP + cb];
            __half2 h0 = __floats2half2_rn((wA0 * acc[nt][0] + wB0 * oB0.x) * inv0,
                                           (wA0 * acc[nt][1] + wB0 * oB0.y) * inv0);
            __half2 h1 = __floats2half2_rn((wA1 * acc[nt][2] + wB1 * oB1.x) * inv1,
                                           (wA1 * acc[nt][3] + wB1 * oB1.y) * inv1);
            *(__half2*)&O[ob0 + cb] = h0;
            *(__half2*)&O[ob1 + cb] = h1;
        }
    }
}

// ---------------- launch -----------------------------------------------------
extern "C" void kernel_launch(void* const* d_in, const int* in_sizes, int n_in,
                              void* d_out, int out_size)
{
    const float* x       = (const float*)d_in[0];
    const float* wq_w    = (const float*)d_in[1];
    const float* wq_b    = (const float*)d_in[2];
    const float* wkv_a_w = (const float*)d_in[3];
    const float* wkv_a_b = (const float*)d_in[4];
    const float* kvn_g   = (const float*)d_in[5];
    const float* kvn_b   = (const float*)d_in[6];
    const float* wk_w    = (const float*)d_in[7];
    const float* wk_b    = (const float*)d_in[8];
    const float* wv_w    = (const float*)d_in[9];
    const float* wv_b    = (const float*)d_in[10];
    const float* wo_w    = (const float*)d_in[11];
    const float* wo_b    = (const float*)d_in[12];
    const float* cosT    = (const float*)d_in[13];
    const float* sinT    = (const float*)d_in[14];
    float* out = (float*)d_out;

    float *gq, *gkv, *gkn, *gv, *gK;
    __half *gc, *gO, *xt, *wqt, *wkvt, *wkt, *wvt, *wot;
    cudaGetSymbolAddress((void**)&gq,   g_q);
    cudaGetSymbolAddress((void**)&gkv,  g_kv);
    cudaGetSymbolAddress((void**)&gc,   g_c);
    cudaGetSymbolAddress((void**)&gkn,  g_kn);
    cudaGetSymbolAddress((void**)&gv,   g_v);
    cudaGetSymbolAddress((void**)&gK,   g_K);
    cudaGetSymbolAddress((void**)&gO,   g_O);
    cudaGetSymbolAddress((void**)&xt,   g_xt);
    cudaGetSymbolAddress((void**)&wqt,  g_wqt);
    cudaGetSymbolAddress((void**)&wkvt, g_wkvt);
    cudaGetSymbolAddress((void**)&wkt,  g_wkt);
    cudaGetSymbolAddress((void**)&wvt,  g_wvt);
    cudaGetSymbolAddress((void**)&wot,  g_wot);

    cudaFuncSetAttribute(gemm_f16_kernel, cudaFuncAttributeMaxDynamicSharedMemorySize, (int)GEMM_SMEM);
    cudaFuncSetAttribute(attn_mma_kernel, cudaFuncAttributeMaxDynamicSharedMemorySize, (int)ATTN_SMEM);

    // 0a) x -> fp16
    {
        int n4 = ROWS * DIM / 4;
        f2h_kernel<<<(n4 + 255) / 256, 256>>>(x, xt, n4);
    }
    // 0b) transpose+round weights  W[K][N] -> Wt[N][K] fp16
    transpose_w_kernel<<<dim3(QCOLS/32,  DIM/32),    256>>>(wq_w,    wqt,  DIM,    QCOLS);
    transpose_w_kernel<<<dim3(KVCOLS/32, DIM/32),    256>>>(wkv_a_w, wkvt, DIM,    KVCOLS);
    transpose_w_kernel<<<dim3((HH*NOPE)/32, KVRANK/32), 256>>>(wk_w, wkt,  KVRANK, HH*NOPE);
    transpose_w_kernel<<<dim3((HH*VHD)/32,  KVRANK/32), 256>>>(wv_w, wvt,  KVRANK, HH*VHD);
    transpose_w_kernel<<<dim3(DIM/32, (HH*VHD)/32),  256>>>(wo_w,    wot,  HH*VHD, DIM);

    // 1) q = x @ wq_w + b
    gemm_f16_kernel<<<dim3(QCOLS/GBN, ROWS/GBM), 256, GEMM_SMEM>>>(wqt, xt, wq_b, gq, ROWS, QCOLS, DIM);
    // 2) kv = x @ wkv_a_w + b
    gemm_f16_kernel<<<dim3(KVCOLS/GBN, ROWS/GBM), 256, GEMM_SMEM>>>(wkvt, xt, wkv_a_b, gkv, ROWS, KVCOLS, DIM);
    // 3) layernorm (fp16 output)
    ln_kernel<<<ROWS, 128>>>(gkv, kvn_g, kvn_b, gc);
    // 4) k_nope = c @ wk_w + b
    gemm_f16_kernel<<<dim3((HH*NOPE)/GBN, ROWS/GBM), 256, GEMM_SMEM>>>(wkt, gc, wk_b, gkn, ROWS, HH*NOPE, KVRANK);
    // 5) v = c @ wv_w + b
    gemm_f16_kernel<<<dim3((HH*VHD)/GBN, ROWS/GBM), 256, GEMM_SMEM>>>(wvt, gc, wv_b, gv, ROWS, HH*VHD, KVRANK);
    // 6) rope + assemble K
    {
        int total = ROWS * HH * 32;
        rope_assemble_kernel<<<(total + 255) / 256, 256>>>(gq, gkv, gkn, cosT, sinT, gK);
    }
    // 7) attention (tf32 mma; fp16 O output)
    attn_mma_kernel<<<dim3(SS/ABQ, HH, BB), 256, ATTN_SMEM>>>(gq, gK, gv, gO);
    // 8) out = O @ wo_w + b
    gemm_f16_kernel<<<dim3(DIM/GBN, ROWS/GBM), 256, GEMM_SMEM>>>(wot, gO, wo_b, out, ROWS, DIM, HH*VHD);
}

// round 13
// speedup vs baseline: 1.5022x; 1.0645x over previous
#include <cuda_runtime.h>
#include <cuda_fp16.h>
#include <cuda_bf16.h>
#include <math.h>
#include <stdint.h>

// ---------------- problem constants ----------------
#define BB    2
#define SS    2048
#define DIM   2048
#define HH    16
#define NOPE  128
#define ROPE  64
#define QKHD  192
#define VHD   128
#define KVRANK 512
#define ROWS  (BB*SS)             // 4096
#define QCOLS (HH*QKHD)           // 3072
#define KVCOLS (KVRANK + HH*ROPE) // 1536

// ---------------- scratch (device globals) ----------------------------------
__device__ float  g_q  [ROWS * QCOLS];
__device__ float  g_kv [ROWS * KVCOLS];
__device__ __half g_c  [ROWS * KVRANK];
__device__ float  g_kn [ROWS * HH * NOPE];
__device__ float  g_v  [ROWS * HH * VHD];
__device__ float  g_K  [ROWS * HH * QKHD];
__device__ __half g_O  [ROWS * HH * VHD];
__device__ __half g_xt   [ROWS * DIM];
__device__ __half g_wqt  [QCOLS * DIM];
__device__ __half g_wkvt [KVCOLS * DIM];
__device__ __half g_wkt  [HH * NOPE * KVRANK];
__device__ __half g_wvt  [HH * VHD * KVRANK];
__device__ __half g_wot  [DIM * HH * VHD];

// ---------------- helpers -----------------------------------------------------
__device__ __forceinline__ void mma_f16(float* d, const uint32_t* a, const uint32_t* b) {
    asm volatile(
        "mma.sync.aligned.m16n8k16.row.col.f32.f16.f16.f32 "
        "{%0,%1,%2,%3}, {%4,%5,%6,%7}, {%8,%9}, {%0,%1,%2,%3};"
        : "+f"(d[0]), "+f"(d[1]), "+f"(d[2]), "+f"(d[3])
        : "r"(a[0]), "r"(a[1]), "r"(a[2]), "r"(a[3]), "r"(b[0]), "r"(b[1]));
}

// ---------------- prep: fp32 -> fp16 (plain layout, activations) ------------
__global__ void f2h_kernel(const float* __restrict__ src,
                           __half* __restrict__ dst, int n4)
{
    int i = blockIdx.x * blockDim.x + threadIdx.x;
    if (i >= n4) return;
    float4 v = *(const float4*)&src[i * 4];
    *(__half2*)&dst[i * 4]     = __floats2half2_rn(v.x, v.y);
    *(__half2*)&dst[i * 4 + 2] = __floats2half2_rn(v.z, v.w);
}

// ---------------- prep: transpose+round weights (W[K][N] -> Wt[N][K] fp16) --
__global__ void transpose_w_kernel(const float* __restrict__ W,
                                   __half* __restrict__ Wt, int K, int N)
{
    __shared__ float t[32][33];
    const int kb0 = blockIdx.y * 32;
    const int nb0 = blockIdx.x * 32;
    const int tid = threadIdx.x;   // 256
    #pragma unroll
    for (int it = 0; it < 4; it++) {
        int kl = (tid >> 5) + it * 8;
        int nl = tid & 31;
        t[kl][nl] = W[(size_t)(kb0 + kl) * N + nb0 + nl];
    }
    __syncthreads();
    #pragma unroll
    for (int it = 0; it < 4; it++) {
        int nl = (tid >> 5) + it * 8;
        int kl = tid & 31;
        Wt[(size_t)(nb0 + nl) * K + kb0 + kl] = __float2half(t[kl][nl]);
    }
}

// ---------------- fp16 tensor-core GEMM (R11, unchanged) --------------------
#define GBM 128
#define GBN 128
#define GBK 32
#define TPAD 40
#define TILE_STAGE (128 * TPAD)
#define GEMM_SMEM ((4 * TILE_STAGE) * sizeof(__half))

__global__ __launch_bounds__(256, 2)
void gemm_f16_kernel(const __half* __restrict__ Wt, const __half* __restrict__ Act,
                     const float* __restrict__ bias, float* __restrict__ C,
                     int M, int N, int K)
{
    extern __shared__ __half sh[];
    __half* As = sh;
    __half* Ws = sh + 2 * TILE_STAGE;

    const int tid  = threadIdx.x;
    const int lane = tid & 31;
    const int warp = tid >> 5;
    const int g  = lane >> 2;
    const int tg = lane & 3;
    const int wm = warp & 3;
    const int wn = warp >> 2;
    const int row0 = blockIdx.y * GBM;
    const int col0 = blockIdx.x * GBN;

    const uint32_t as_base = (uint32_t)__cvta_generic_to_shared(As);
    const uint32_t ws_base = (uint32_t)__cvta_generic_to_shared(Ws);

    float acc[2][8][4];
    #pragma unroll
    for (int mt = 0; mt < 2; mt++)
        #pragma unroll
        for (int nt = 0; nt < 8; nt++)
            #pragma unroll
            for (int i = 0; i < 4; i++) acc[mt][nt][i] = 0.f;

#define STAGE_LOAD(s_, kt_) do {                                               \
    _Pragma("unroll")                                                          \
    for (int n_ = 0; n_ < 2; n_++) {                                           \
        int i_ = tid + n_ * 256; int r_ = i_ >> 2; int c_ = (i_ & 3) * 8;      \
        uint32_t da_ = as_base + (uint32_t)(((s_) * TILE_STAGE + r_ * TPAD + c_) * 2); \
        asm volatile("cp.async.cg.shared.global [%0], [%1], 16;"               \
                     :: "r"(da_), "l"(Act + (size_t)(row0 + r_) * K + (kt_) * GBK + c_)); \
        uint32_t dw_ = ws_base + (uint32_t)(((s_) * TILE_STAGE + r_ * TPAD + c_) * 2); \
        asm volatile("cp.async.cg.shared.global [%0], [%1], 16;"               \
                     :: "r"(dw_), "l"(Wt + (size_t)(col0 + r_) * K + (kt_) * GBK + c_)); \
    }                                                                          \
    asm volatile("cp.async.commit_group;");                                    \
} while (0)

    const int KT = K / GBK;
    STAGE_LOAD(0, 0);

    for (int kt = 0; kt < KT; kt++) {
        const int s = kt & 1;
        if (kt + 1 < KT) {
            STAGE_LOAD(1 - s, kt + 1);
            asm volatile("cp.async.wait_group 1;");
        } else {
            asm volatile("cp.async.wait_group 0;");
        }
        __syncthreads();

        const __half* Asl = As + s * TILE_STAGE;
        const __half* Wsl = Ws + s * TILE_STAGE;

        #pragma unroll
        for (int ks = 0; ks < 2; ks++) {
            const int kk = ks * 16 + 2 * tg;
            uint32_t af[2][4];
            #pragma unroll
            for (int mt = 0; mt < 2; mt++) {
                int row = wm * 32 + mt * 16 + g;
                af[mt][0] = *(const uint32_t*)&Asl[row * TPAD + kk];
                af[mt][1] = *(const uint32_t*)&Asl[(row + 8) * TPAD + kk];
                af[mt][2] = *(const uint32_t*)&Asl[row * TPAD + kk + 8];
                af[mt][3] = *(const uint32_t*)&Asl[(row + 8) * TPAD + kk + 8];
            }
            #pragma unroll
            for (int nt = 0; nt < 8; nt++) {
                int col = wn * 64 + nt * 8 + g;
                uint32_t bf[2];
                bf[0] = *(const uint32_t*)&Wsl[col * TPAD + kk];
                bf[1] = *(const uint32_t*)&Wsl[col * TPAD + kk + 8];
                #pragma unroll
                for (int mt = 0; mt < 2; mt++)
                    mma_f16(acc[mt][nt], af[mt], bf);
            }
        }
        __syncthreads();
    }
#undef STAGE_LOAD

    #pragma unroll
    for (int mt = 0; mt < 2; mt++) {
        int r = row0 + wm * 32 + mt * 16 + g;
        #pragma unroll
        for (int nt = 0; nt < 8; nt++) {
            int c = col0 + wn * 64 + nt * 8 + tg * 2;
            float b0 = bias[c], b1 = bias[c + 1];
            float2 v0 = make_float2(acc[mt][nt][0] + b0, acc[mt][nt][1] + b1);
            float2 v1 = make_float2(acc[mt][nt][2] + b0, acc[mt][nt][3] + b1);
            *(float2*)&C[(size_t)r * N + c]       = v0;
            *(float2*)&C[(size_t)(r + 8) * N + c] = v1;
        }
    }
}

// ---------------- LayerNorm (fp16 output) -----------------------------------
__global__ void ln_kernel(const float* __restrict__ kv,
                          const float* __restrict__ gamma,
                          const float* __restrict__ beta,
                          __half* __restrict__ out)
{
    const int row = blockIdx.x;
    const float* src = kv + (size_t)row * KVCOLS + HH * ROPE;
    __half* dst = out + (size_t)row * KVRANK;
    const int tid = threadIdx.x;

    float v[4];
    float s = 0.f, s2 = 0.f;
    #pragma unroll
    for (int i = 0; i < 4; i++) {
        v[i] = src[tid + i * 128];
        s += v[i];
        s2 += v[i] * v[i];
    }
    __shared__ float rs[128], rs2[128];
    rs[tid] = s; rs2[tid] = s2;
    __syncthreads();
    for (int o = 64; o > 0; o >>= 1) {
        if (tid < o) { rs[tid] += rs[tid + o]; rs2[tid] += rs2[tid + o]; }
        __syncthreads();
    }
    float mean = rs[0] * (1.f / 512.f);
    float var  = rs2[0] * (1.f / 512.f) - mean * mean;
    float rstd = rsqrtf(var + 1e-5f);
    #pragma unroll
    for (int i = 0; i < 4; i++) {
        int c = tid + i * 128;
        dst[c] = __float2half((v[i] - mean) * rstd * gamma[c] + beta[c]);
    }
}

// ---------------- RoPE + K assembly (REFERENCE reshape semantics) -----------
__global__ void rope_assemble_kernel(float* __restrict__ q,
                                     const float* __restrict__ kv,
                                     const float* __restrict__ knope,
                                     const float* __restrict__ cosT,
                                     const float* __restrict__ sinT,
                                     float* __restrict__ Kout)
{
    int idx = blockIdx.x * blockDim.x + threadIdx.x;
    if (idx >= ROWS * HH * 32) return;
    int p   = idx & 31;
    int h   = (idx >> 5) & 15;
    int row = idx >> 9;
    int s   = row & (SS - 1);

    float cv = cosT[s * 32 + p];
    float sv = sinT[s * 32 + p];

    size_t qb = (size_t)row * QCOLS + h * QKHD + NOPE + 2 * p;
    float a = q[qb], b = q[qb + 1];
    q[qb]     = a * cv - b * sv;
    q[qb + 1] = a * sv + b * cv;

    const float* knr = knope + (size_t)row * (HH * NOPE);
    const float* krr = kv + (size_t)row * KVCOLS;
    size_t ko = ((size_t)row * HH + h) * QKHD;

    {
        int gg = h * QKHD + p * 4;
        float4 nv;
        if (gg < HH * NOPE) nv = *(const float4*)&knr[gg];
        else                nv = *(const float4*)&krr[gg - HH * NOPE];
        *(float4*)&Kout[ko + p * 4] = nv;
    }
    {
        int gg = h * QKHD + NOPE + 2 * p;
        float ka, kb;
        if (gg < HH * NOPE) { ka = knr[gg];              kb = knr[gg + 1]; }
        else                { ka = krr[gg - HH * NOPE];  kb = krr[gg - HH * NOPE + 1]; }
        Kout[ko + NOPE + 2 * p]     = ka * cv - kb * sv;
        Kout[ko + NOPE + 2 * p + 1] = ka * sv + kb * cv;
    }
}

// ---------------- fp16 tensor-core causal flash attention -------------------
// BQ=64, BKT=64, 256 threads = 8 warps (wq 0..3 x kh 0..1).
// QK: m16n8k16 f16 (12 steps).  PV: m16n8k16 f16 over transposed V (2 steps).
#define ABQ 64
#define ABK 64
#define QSPh 200      // halves per Q/K row
#define VTP  72       // halves per V^T row (kv dim padded)
#define PSPh 72       // halves per P row (64 kv cols + 8 pad)  [R12 bug: was 40]
#define OSP  132      // floats per merge row (aliases dead K/V smem)
#define SM_Q 0
#define SM_K (ABQ * QSPh)                 // 12800
#define SM_VT (SM_K + ABK * QSPh)         // 25600
#define SM_P (SM_VT + 128 * VTP)          // 34816
#define ATTN_HALVES (SM_P + ABQ * PSPh)   // 39424
#define ATTN_SMEM (ATTN_HALVES * sizeof(__half))

__global__ __launch_bounds__(256, 2)
void attn_f16_kernel(const float* __restrict__ Q,
                     const float* __restrict__ Kf,
                     const float* __restrict__ V,
                     __half* __restrict__ O)
{
    const int q0 = blockIdx.x * ABQ;
    const int h  = blockIdx.y;
    const int b  = blockIdx.z;

    extern __shared__ __half smh[];
    __half* Qs  = smh + SM_Q;
    __half* Ks  = smh + SM_K;
    __half* Vst = smh + SM_VT;
    __half* Ps  = smh + SM_P;

    const int tid  = threadIdx.x;
    const int lane = tid & 31;
    const int wid  = tid >> 5;
    const int g    = lane >> 2;
    const int tg   = lane & 3;
    const int wq   = wid & 3;
    const int kh   = wid >> 2;
    const int rA   = wq * 16 + g;
    const float scale = 0.07216878364870322f;

    // ---- stage Q (scaled fp16) ----
    const float* Qg = Q + (((size_t)(b * SS + q0)) * HH + h) * QKHD;
    #pragma unroll
    for (int n = 0; n < 12; n++) {
        int i = tid + n * 256;
        int r = i / 48, d4 = (i % 48) * 4;
        float4 v = *(const float4*)&Qg[(size_t)r * (HH * QKHD) + d4];
        *(__half2*)&Qs[r * QSPh + d4]     = __floats2half2_rn(v.x * scale, v.y * scale);
        *(__half2*)&Qs[r * QSPh + d4 + 2] = __floats2half2_rn(v.z * scale, v.w * scale);
    }

    float m0 = -INFINITY, m1 = -INFINITY, l0 = 0.f, l1 = 0.f;
    float acc[16][4];
    #pragma unroll
    for (int nt = 0; nt < 16; nt++)
        #pragma unroll
        for (int i = 0; i < 4; i++) acc[nt][i] = 0.f;

    const int jend = blockIdx.x;
    for (int j = 0; j <= jend; j++) {
        const int k0 = j * ABK;
        __syncthreads();
        // ---- stage K (fp16) ----
        const float* Kg = Kf + (((size_t)(b * SS + k0)) * HH + h) * QKHD;
        #pragma unroll
        for (int n = 0; n < 12; n++) {
            int i = tid + n * 256;
            int r = i / 48, d4 = (i % 48) * 4;
            float4 v = *(const float4*)&Kg[(size_t)r * (HH * QKHD) + d4];
            *(__half2*)&Ks[r * QSPh + d4]     = __floats2half2_rn(v.x, v.y);
            *(__half2*)&Ks[r * QSPh + d4 + 2] = __floats2half2_rn(v.z, v.w);
        }
        // ---- stage V transposed: Vst[d][kv] fp16 ----
        const float* Vg = V + (((size_t)(b * SS + k0)) * HH + h) * VHD;
        #pragma unroll
        for (int n = 0; n < 4; n++) {
            int i = tid + n * 256;          // 1024 items: d4 = i>>5, kvp = i&31
            int d4 = i >> 5, kv = (i & 31) * 2;
            float4 v0 = *(const float4*)&Vg[(size_t)kv * (HH * VHD) + d4 * 4];
            float4 v1 = *(const float4*)&Vg[(size_t)(kv + 1) * (HH * VHD) + d4 * 4];
            *(__half2*)&Vst[(d4 * 4 + 0) * VTP + kv] = __floats2half2_rn(v0.x, v1.x);
            *(__half2*)&Vst[(d4 * 4 + 1) * VTP + kv] = __floats2half2_rn(v0.y, v1.y);
            *(__half2*)&Vst[(d4 * 4 + 2) * VTP + kv] = __floats2half2_rn(v0.z, v1.z);
            *(__half2*)&Vst[(d4 * 4 + 3) * VTP + kv] = __floats2half2_rn(v0.w, v1.w);
        }
        __syncthreads();

        // ---- QK^T: 16x32 per warp, f16 mma (12 k-steps) ----
        float sc[4][4];
        #pragma unroll
        for (int nt = 0; nt < 4; nt++)
            #pragma unroll
            for (int i = 0; i < 4; i++) sc[nt][i] = 0.f;

        #pragma unroll
        for (int kc = 0; kc < 12; kc++) {
            const int kk = kc * 16 + 2 * tg;
            uint32_t af[4];
            af[0] = *(const uint32_t*)&Qs[rA * QSPh + kk];
            af[1] = *(const uint32_t*)&Qs[(rA + 8) * QSPh + kk];
            af[2] = *(const uint32_t*)&Qs[rA * QSPh + kk + 8];
            af[3] = *(const uint32_t*)&Qs[(rA + 8) * QSPh + kk + 8];
            #pragma unroll
            for (int nt = 0; nt < 4; nt++) {
                int kvr = kh * 32 + nt * 8 + g;
                uint32_t bf[2];
                bf[0] = *(const uint32_t*)&Ks[kvr * QSPh + kk];
                bf[1] = *(const uint32_t*)&Ks[kvr * QSPh + kk + 8];
                mma_f16(sc[nt], af, bf);
            }
        }

        // ---- causal mask (diagonal block) ----
        if (j == jend) {
            #pragma unroll
            for (int nt = 0; nt < 4; nt++) {
                int colb = k0 + kh * 32 + nt * 8 + 2 * tg;
                int row0g = q0 + rA, row1g = q0 + rA + 8;
                if (colb     > row0g) sc[nt][0] = -INFINITY;
                if (colb + 1 > row0g) sc[nt][1] = -INFINITY;
                if (colb     > row1g) sc[nt][2] = -INFINITY;
                if (colb + 1 > row1g) sc[nt][3] = -INFINITY;
            }
        }

        // ---- online softmax (rows warp-local, tg-quad reduce) ----
        float ml0 = -INFINITY, ml1 = -INFINITY;
        #pragma unroll
        for (int nt = 0; nt < 4; nt++) {
            ml0 = fmaxf(ml0, fmaxf(sc[nt][0], sc[nt][1]));
            ml1 = fmaxf(ml1, fmaxf(sc[nt][2], sc[nt][3]));
        }
        ml0 = fmaxf(ml0, __shfl_xor_sync(0xffffffffu, ml0, 1));
        ml0 = fmaxf(ml0, __shfl_xor_sync(0xffffffffu, ml0, 2));
        ml1 = fmaxf(ml1, __shfl_xor_sync(0xffffffffu, ml1, 1));
        ml1 = fmaxf(ml1, __shfl_xor_sync(0xffffffffu, ml1, 2));
        float mn0 = fmaxf(m0, ml0), mn1 = fmaxf(m1, ml1);
        float mr0 = (mn0 == -INFINITY) ? 0.f : mn0;
        float mr1 = (mn1 == -INFINITY) ? 0.f : mn1;
        float a0 = __expf(m0 - mr0);
        float a1 = __expf(m1 - mr1);

        float ll0 = 0.f, ll1 = 0.f;
        #pragma unroll
        for (int nt = 0; nt < 4; nt++) {
            __half2 h0 = __floats2half2_rn(__expf(sc[nt][0] - mr0), __expf(sc[nt][1] - mr0));
            __half2 h1 = __floats2half2_rn(__expf(sc[nt][2] - mr1), __expf(sc[nt][3] - mr1));
            int cb = kh * 32 + nt * 8 + 2 * tg;
            *(__half2*)&Ps[rA * PSPh + cb]       = h0;
            *(__half2*)&Ps[(rA + 8) * PSPh + cb] = h1;
            float2 f0 = __half22float2(h0);
            float2 f1 = __half22float2(h1);
            ll0 += f0.x + f0.y;
            ll1 += f1.x + f1.y;
        }
        ll0 += __shfl_xor_sync(0xffffffffu, ll0, 1);
        ll0 += __shfl_xor_sync(0xffffffffu, ll0, 2);
        ll1 += __shfl_xor_sync(0xffffffffu, ll1, 1);
        ll1 += __shfl_xor_sync(0xffffffffu, ll1, 2);

        m0 = mn0; m1 = mn1;
        l0 = l0 * a0 + ll0;
        l1 = l1 * a1 + ll1;

        #pragma unroll
        for (int nt = 0; nt < 16; nt++) {
            acc[nt][0] *= a0; acc[nt][1] *= a0;
            acc[nt][2] *= a1; acc[nt][3] *= a1;
        }
        __syncwarp();

        // ---- PV: 16x128 per warp over its 32-kv half, f16 mma (2 k-steps) ----
        #pragma unroll
        for (int kc = 0; kc < 2; kc++) {
            const int kk = kh * 32 + kc * 16 + 2 * tg;
            uint32_t af[4];
            af[0] = *(const uint32_t*)&Ps[rA * PSPh + kk];
            af[1] = *(const uint32_t*)&Ps[(rA + 8) * PSPh + kk];
            af[2] = *(const uint32_t*)&Ps[rA * PSPh + kk + 8];
            af[3] = *(const uint32_t*)&Ps[(rA + 8) * PSPh + kk + 8];
            #pragma unroll
            for (int nt = 0; nt < 16; nt++) {
                int d = nt * 8 + g;
                uint32_t bf[2];
                bf[0] = *(const uint32_t*)&Vst[d * VTP + kk];
                bf[1] = *(const uint32_t*)&Vst[d * VTP + kk + 8];
                mma_f16(acc[nt], af, bf);
            }
        }
        __syncwarp();
    }

    // ---- merge kv halves; write fp16 O ----
    __syncthreads();
    float* Osh = (float*)(smh + SM_K);      // aliases dead Ks+Vst (33.8KB < 44KB span)
    float* msh = (float*)(smh + SM_P);      // aliases dead Ps
    float* lsh = msh + 64;

    if (kh == 1) {
        if (tg == 0) {
            msh[rA] = m0;  msh[rA + 8] = m1;
            lsh[rA] = l0;  lsh[rA + 8] = l1;
        }
        #pragma unroll
        for (int nt = 0; nt < 16; nt++) {
            int cb = nt * 8 + 2 * tg;
            *(float2*)&Osh[rA * OSP + cb]       = make_float2(acc[nt][0], acc[nt][1]);
            *(float2*)&Osh[(rA + 8) * OSP + cb] = make_float2(acc[nt][2], acc[nt][3]);
        }
    }
    __syncthreads();
    if (kh == 0) {
        float mB0 = msh[rA], mB1 = msh[rA + 8];
        float lB0 = lsh[rA], lB1 = lsh[rA + 8];
        float mm0 = fmaxf(m0, mB0), mm1 = fmaxf(m1, mB1);
        float wA0 = __expf(m0 - mm0),  wB0 = __expf(mB0 - mm0);
        float wA1 = __expf(m1 - mm1),  wB1 = __expf(mB1 - mm1);
        float inv0 = 1.f / (wA0 * l0 + wB0 * lB0);
        float inv1 = 1.f / (wA1 * l1 + wB1 * lB1);

        size_t ob0 = (((size_t)(b * SS + q0 + rA)) * HH + h) * VHD;
        size_t ob1 = (((size_t)(b * SS + q0 + rA + 8)) * HH + h) * VHD;
        #pragma unroll
        for (int nt = 0; nt < 16; nt++) {
            int cb = nt * 8 + 2 * tg;
            float2 oB0 = *(float2*)&Osh[rA * OSP + cb];
            float2 oB1 = *(float2*)&Osh[(rA + 8) * OSP + cb];
            __half2 h0 = __floats2half2_rn((wA0 * acc[nt][0] + wB0 * oB0.x) * inv0,
                                           (wA0 * acc[nt][1] + wB0 * oB0.y) * inv0);
            __half2 h1 = __floats2half2_rn((wA1 * acc[nt][2] + wB1 * oB1.x) * inv1,
                                           (wA1 * acc[nt][3] + wB1 * oB1.y) * inv1);
            *(__half2*)&O[ob0 + cb] = h0;
            *(__half2*)&O[ob1 + cb] = h1;
        }
    }
}

// ---------------- launch -----------------------------------------------------
extern "C" void kernel_launch(void* const* d_in, const int* in_sizes, int n_in,
                              void* d_out, int out_size)
{
    const float* x       = (const float*)d_in[0];
    const float* wq_w    = (const float*)d_in[1];
    const float* wq_b    = (const float*)d_in[2];
    const float* wkv_a_w = (const float*)d_in[3];
    const float* wkv_a_b = (const float*)d_in[4];
    const float* kvn_g   = (const float*)d_in[5];
    const float* kvn_b   = (const float*)d_in[6];
    const float* wk_w    = (const float*)d_in[7];
    const float* wk_b    = (const float*)d_in[8];
    const float* wv_w    = (const float*)d_in[9];
    const float* wv_b    = (const float*)d_in[10];
    const float* wo_w    = (const float*)d_in[11];
    const float* wo_b    = (const float*)d_in[12];
    const float* cosT    = (const float*)d_in[13];
    const float* sinT    = (const float*)d_in[14];
    float* out = (float*)d_out;

    float *gq, *gkv, *gkn, *gv, *gK;
    __half *gc, *gO, *xt, *wqt, *wkvt, *wkt, *wvt, *wot;
    cudaGetSymbolAddress((void**)&gq,   g_q);
    cudaGetSymbolAddress((void**)&gkv,  g_kv);
    cudaGetSymbolAddress((void**)&gc,   g_c);
    cudaGetSymbolAddress((void**)&gkn,  g_kn);
    cudaGetSymbolAddress((void**)&gv,   g_v);
    cudaGetSymbolAddress((void**)&gK,   g_K);
    cudaGetSymbolAddress((void**)&gO,   g_O);
    cudaGetSymbolAddress((void**)&xt,   g_xt);
    cudaGetSymbolAddress((void**)&wqt,  g_wqt);
    cudaGetSymbolAddress((void**)&wkvt, g_wkvt);
    cudaGetSymbolAddress((void**)&wkt,  g_wkt);
    cudaGetSymbolAddress((void**)&wvt,  g_wvt);
    cudaGetSymbolAddress((void**)&wot,  g_wot);

    cudaFuncSetAttribute(gemm_f16_kernel, cudaFuncAttributeMaxDynamicSharedMemorySize, (int)GEMM_SMEM);
    cudaFuncSetAttribute(attn_f16_kernel, cudaFuncAttributeMaxDynamicSharedMemorySize, (int)ATTN_SMEM);

    // 0a) x -> fp16
    {
        int n4 = ROWS * DIM / 4;
        f2h_kernel<<<(n4 + 255) / 256, 256>>>(x, xt, n4);
    }
    // 0b) transpose+round weights  W[K][N] -> Wt[N][K] fp16
    transpose_w_kernel<<<dim3(QCOLS/32,  DIM/32),    256>>>(wq_w,    wqt,  DIM,    QCOLS);
    transpose_w_kernel<<<dim3(KVCOLS/32, DIM/32),    256>>>(wkv_a_w, wkvt, DIM,    KVCOLS);
    transpose_w_kernel<<<dim3((HH*NOPE)/32, KVRANK/32), 256>>>(wk_w, wkt,  KVRANK, HH*NOPE);
    transpose_w_kernel<<<dim3((HH*VHD)/32,  KVRANK/32), 256>>>(wv_w, wvt,  KVRANK, HH*VHD);
    transpose_w_kernel<<<dim3(DIM/32, (HH*VHD)/32),  256>>>(wo_w,    wot,  HH*VHD, DIM);

    // 1) q = x @ wq_w + b
    gemm_f16_kernel<<<dim3(QCOLS/GBN, ROWS/GBM), 256, GEMM_SMEM>>>(wqt, xt, wq_b, gq, ROWS, QCOLS, DIM);
    // 2) kv = x @ wkv_a_w + b
    gemm_f16_kernel<<<dim3(KVCOLS/GBN, ROWS/GBM), 256, GEMM_SMEM>>>(wkvt, xt, wkv_a_b, gkv, ROWS, KVCOLS, DIM);
    // 3) layernorm (fp16 output)
    ln_kernel<<<ROWS, 128>>>(gkv, kvn_g, kvn_b, gc);
    // 4) k_nope = c @ wk_w + b
    gemm_f16_kernel<<<dim3((HH*NOPE)/GBN, ROWS/GBM), 256, GEMM_SMEM>>>(wkt, gc, wk_b, gkn, ROWS, HH*NOPE, KVRANK);
    // 5) v = c @ wv_w + b
    gemm_f16_kernel<<<dim3((HH*VHD)/GBN, ROWS/GBM), 256, GEMM_SMEM>>>(wvt, gc, wv_b, gv, ROWS, HH*VHD, KVRANK);
    // 6) rope + assemble K
    {
        int total = ROWS * HH * 32;
        rope_assemble_kernel<<<(total + 255) / 256, 256>>>(gq, gkv, gkn, cosT, sinT, gK);
    }
    // 7) attention (fp16 mma; fp16 O output)
    attn_f16_kernel<<<dim3(SS/ABQ, HH, BB), 256, ATTN_SMEM>>>(gq, gK, gv, gO);
    // 8) out = O @ wo_w + b
    gemm_f16_kernel<<<dim3(DIM/GBN, ROWS/GBM), 256, GEMM_SMEM>>>(wot, gO, wo_b, out, ROWS, DIM, HH*VHD);
}

// round 16
// speedup vs baseline: 1.5500x; 1.0318x over previous
#include <cuda_runtime.h>
#include <cuda_fp16.h>
#include <cuda_bf16.h>
#include <math.h>
#include <stdint.h>

// ---------------- problem constants ----------------
#define BB    2
#define SS    2048
#define DIM   2048
#define HH    16
#define NOPE  128
#define ROPE  64
#define QKHD  192
#define VHD   128
#define KVRANK 512
#define ROWS  (BB*SS)             // 4096
#define QCOLS (HH*QKHD)           // 3072
#define KVCOLS (KVRANK + HH*ROPE) // 1536

// ---------------- scratch (device globals) ----------------------------------
__device__ float  g_q  [ROWS * QCOLS];      // q proj (fp32, pre-rope)
__device__ float  g_kv [ROWS * KVCOLS];
__device__ __half g_c  [ROWS * KVRANK];
__device__ float  g_kn [ROWS * HH * NOPE];
__device__ __half g_vh [ROWS * HH * VHD];   // fp16 V
__device__ __half g_Qh [ROWS * HH * QKHD];  // fp16 Q, rope'd + pre-scaled
__device__ __half g_Kh [ROWS * HH * QKHD];  // fp16 K, assembled + rope'd
__device__ __half g_O  [ROWS * HH * VHD];
__device__ __half g_xt   [ROWS * DIM];
__device__ __half g_wqt  [QCOLS * DIM];
__device__ __half g_wkvt [KVCOLS * DIM];
__device__ __half g_wkt  [HH * NOPE * KVRANK];
__device__ __half g_wvt  [HH * VHD * KVRANK];
__device__ __half g_wot  [DIM * HH * VHD];

// ---------------- helpers -----------------------------------------------------
__device__ __forceinline__ void mma_f16(float* d, const uint32_t* a, const uint32_t* b) {
    asm volatile(
        "mma.sync.aligned.m16n8k16.row.col.f32.f16.f16.f32 "
        "{%0,%1,%2,%3}, {%4,%5,%6,%7}, {%8,%9}, {%0,%1,%2,%3};"
        : "+f"(d[0]), "+f"(d[1]), "+f"(d[2]), "+f"(d[3])
        : "r"(a[0]), "r"(a[1]), "r"(a[2]), "r"(a[3]), "r"(b[0]), "r"(b[1]));
}

// ---------------- prep: fp32 -> fp16 (plain layout, activations) ------------
__global__ void f2h_kernel(const float* __restrict__ src,
                           __half* __restrict__ dst, int n4)
{
    int i = blockIdx.x * blockDim.x + threadIdx.x;
    if (i >= n4) return;
    float4 v = *(const float4*)&src[i * 4];
    *(__half2*)&dst[i * 4]     = __floats2half2_rn(v.x, v.y);
    *(__half2*)&dst[i * 4 + 2] = __floats2half2_rn(v.z, v.w);
}

// ---------------- prep: transpose+round weights (W[K][N] -> Wt[N][K] fp16) --
__global__ void transpose_w_kernel(const float* __restrict__ W,
                                   __half* __restrict__ Wt, int K, int N)
{
    __shared__ float t[32][33];
    const int kb0 = blockIdx.y * 32;
    const int nb0 = blockIdx.x * 32;
    const int tid = threadIdx.x;   // 256
    #pragma unroll
    for (int it = 0; it < 4; it++) {
        int kl = (tid >> 5) + it * 8;
        int nl = tid & 31;
        t[kl][nl] = W[(size_t)(kb0 + kl) * N + nb0 + nl];
    }
    __syncthreads();
    #pragma unroll
    for (int it = 0; it < 4; it++) {
        int nl = (tid >> 5) + it * 8;
        int kl = tid & 31;
        Wt[(size_t)(nb0 + nl) * K + kb0 + kl] = __float2half(t[kl][nl]);
    }
}

// ---------------- fp16 tensor-core GEMM (fp32 output) -----------------------
#define GBM 128
#define GBN 128
#define GBK 32
#define TPAD 40
#define TILE_STAGE (128 * TPAD)
#define GEMM_SMEM ((4 * TILE_STAGE) * sizeof(__half))

#define STAGE_LOAD(s_, kt_) do {                                               \
    _Pragma("unroll")                                                          \
    for (int n_ = 0; n_ < 2; n_++) {                                           \
        int i_ = tid + n_ * 256; int r_ = i_ >> 2; int c_ = (i_ & 3) * 8;      \
        uint32_t da_ = as_base + (uint32_t)(((s_) * TILE_STAGE + r_ * TPAD + c_) * 2); \
        asm volatile("cp.async.cg.shared.global [%0], [%1], 16;"               \
                     :: "r"(da_), "l"(Act + (size_t)(row0 + r_) * K + (kt_) * GBK + c_)); \
        uint32_t dw_ = ws_base + (uint32_t)(((s_) * TILE_STAGE + r_ * TPAD + c_) * 2); \
        asm volatile("cp.async.cg.shared.global [%0], [%1], 16;"               \
                     :: "r"(dw_), "l"(Wt + (size_t)(col0 + r_) * K + (kt_) * GBK + c_)); \
    }                                                                          \
    asm volatile("cp.async.commit_group;");                                    \
} while (0)

__global__ __launch_bounds__(256, 2)
void gemm_f16_kernel(const __half* __restrict__ Wt, const __half* __restrict__ Act,
                     const float* __restrict__ bias, float* __restrict__ C,
                     int M, int N, int K)
{
    extern __shared__ __half sh[];
    __half* As = sh;
    __half* Ws = sh + 2 * TILE_STAGE;

    const int tid  = threadIdx.x;
    const int lane = tid & 31;
    const int warp = tid >> 5;
    const int g  = lane >> 2;
    const int tg = lane & 3;
    const int wm = warp & 3;
    const int wn = warp >> 2;
    const int row0 = blockIdx.y * GBM;
    const int col0 = blockIdx.x * GBN;

    const uint32_t as_base = (uint32_t)__cvta_generic_to_shared(As);
    const uint32_t ws_base = (uint32_t)__cvta_generic_to_shared(Ws);

    float acc[2][8][4];
    #pragma unroll
    for (int mt = 0; mt < 2; mt++)
        #pragma unroll
        for (int nt = 0; nt < 8; nt++)
            #pragma unroll
            for (int i = 0; i < 4; i++) acc[mt][nt][i] = 0.f;

    const int KT = K / GBK;
    STAGE_LOAD(0, 0);

    for (int kt = 0; kt < KT; kt++) {
        const int s = kt & 1;
        if (kt + 1 < KT) {
            STAGE_LOAD(1 - s, kt + 1);
            asm volatile("cp.async.wait_group 1;");
        } else {
            asm volatile("cp.async.wait_group 0;");
        }
        __syncthreads();

        const __half* Asl = As + s * TILE_STAGE;
        const __half* Wsl = Ws + s * TILE_STAGE;

        #pragma unroll
        for (int ks = 0; ks < 2; ks++) {
            const int kk = ks * 16 + 2 * tg;
            uint32_t af[2][4];
            #pragma unroll
            for (int mt = 0; mt < 2; mt++) {
                int row = wm * 32 + mt * 16 + g;
                af[mt][0] = *(const uint32_t*)&Asl[row * TPAD + kk];
                af[mt][1] = *(const uint32_t*)&Asl[(row + 8) * TPAD + kk];
                af[mt][2] = *(const uint32_t*)&Asl[row * TPAD + kk + 8];
                af[mt][3] = *(const uint32_t*)&Asl[(row + 8) * TPAD + kk + 8];
            }
            #pragma unroll
            for (int nt = 0; nt < 8; nt++) {
                int col = wn * 64 + nt * 8 + g;
                uint32_t bf[2];
                bf[0] = *(const uint32_t*)&Wsl[col * TPAD + kk];
                bf[1] = *(const uint32_t*)&Wsl[col * TPAD + kk + 8];
                #pragma unroll
                for (int mt = 0; mt < 2; mt++)
                    mma_f16(acc[mt][nt], af[mt], bf);
            }
        }
        __syncthreads();
    }

    #pragma unroll
    for (int mt = 0; mt < 2; mt++) {
        int r = row0 + wm * 32 + mt * 16 + g;
        #pragma unroll
        for (int nt = 0; nt < 8; nt++) {
            int c = col0 + wn * 64 + nt * 8 + tg * 2;
            float b0 = bias[c], b1 = bias[c + 1];
            float2 v0 = make_float2(acc[mt][nt][0] + b0, acc[mt][nt][1] + b1);
            float2 v1 = make_float2(acc[mt][nt][2] + b0, acc[mt][nt][3] + b1);
            *(float2*)&C[(size_t)r * N + c]       = v0;
            *(float2*)&C[(size_t)(r + 8) * N + c] = v1;
        }
    }
}

// ---------------- fp16 tensor-core GEMM (fp16 output) -----------------------
__global__ __launch_bounds__(256, 2)
void gemm_f16_hout_kernel(const __half* __restrict__ Wt, const __half* __restrict__ Act,
                          const float* __restrict__ bias, __half* __restrict__ C,
                          int M, int N, int K)
{
    extern __shared__ __half sh[];
    __half* As = sh;
    __half* Ws = sh + 2 * TILE_STAGE;

    const int tid  = threadIdx.x;
    const int lane = tid & 31;
    const int warp = tid >> 5;
    const int g  = lane >> 2;
    const int tg = lane & 3;
    const int wm = warp & 3;
    const int wn = warp >> 2;
    const int row0 = blockIdx.y * GBM;
    const int col0 = blockIdx.x * GBN;

    const uint32_t as_base = (uint32_t)__cvta_generic_to_shared(As);
    const uint32_t ws_base = (uint32_t)__cvta_generic_to_shared(Ws);

    float acc[2][8][4];
    #pragma unroll
    for (int mt = 0; mt < 2; mt++)
        #pragma unroll
        for (int nt = 0; nt < 8; nt++)
            #pragma unroll
            for (int i = 0; i < 4; i++) acc[mt][nt][i] = 0.f;

    const int KT = K / GBK;
    STAGE_LOAD(0, 0);

    for (int kt = 0; kt < KT; kt++) {
        const int s = kt & 1;
        if (kt + 1 < KT) {
            STAGE_LOAD(1 - s, kt + 1);
            asm volatile("cp.async.wait_group 1;");
        } else {
            asm volatile("cp.async.wait_group 0;");
        }
        __syncthreads();

        const __half* Asl = As + s * TILE_STAGE;
        const __half* Wsl = Ws + s * TILE_STAGE;

        #pragma unroll
        for (int ks = 0; ks < 2; ks++) {
            const int kk = ks * 16 + 2 * tg;
            uint32_t af[2][4];
            #pragma unroll
            for (int mt = 0; mt < 2; mt++) {
                int row = wm * 32 + mt * 16 + g;
                af[mt][0] = *(const uint32_t*)&Asl[row * TPAD + kk];
                af[mt][1] = *(const uint32_t*)&Asl[(row + 8) * TPAD + kk];
                af[mt][2] = *(const uint32_t*)&Asl[row * TPAD + kk + 8];
                af[mt][3] = *(const uint32_t*)&Asl[(row + 8) * TPAD + kk + 8];
            }
            #pragma unroll
            for (int nt = 0; nt < 8; nt++) {
                int col = wn * 64 + nt * 8 + g;
                uint32_t bf[2];
                bf[0] = *(const uint32_t*)&Wsl[col * TPAD + kk];
                bf[1] = *(const uint32_t*)&Wsl[col * TPAD + kk + 8];
                #pragma unroll
                for (int mt = 0; mt < 2; mt++)
                    mma_f16(acc[mt][nt], af[mt], bf);
            }
        }
        __syncthreads();
    }

    #pragma unroll
    for (int mt = 0; mt < 2; mt++) {
        int r = row0 + wm * 32 + mt * 16 + g;
        #pragma unroll
        for (int nt = 0; nt < 8; nt++) {
            int c = col0 + wn * 64 + nt * 8 + tg * 2;
            float b0 = bias[c], b1 = bias[c + 1];
            *(__half2*)&C[(size_t)r * N + c] =
                __floats2half2_rn(acc[mt][nt][0] + b0, acc[mt][nt][1] + b1);
            *(__half2*)&C[(size_t)(r + 8) * N + c] =
                __floats2half2_rn(acc[mt][nt][2] + b0, acc[mt][nt][3] + b1);
        }
    }
}
#undef STAGE_LOAD

// ---------------- LayerNorm (fp16 output) -----------------------------------
__global__ void ln_kernel(const float* __restrict__ kv,
                          const float* __restrict__ gamma,
                          const float* __restrict__ beta,
                          __half* __restrict__ out)
{
    const int row = blockIdx.x;
    const float* src = kv + (size_t)row * KVCOLS + HH * ROPE;
    __half* dst = out + (size_t)row * KVRANK;
    const int tid = threadIdx.x;

    float v[4];
    float s = 0.f, s2 = 0.f;
    #pragma unroll
    for (int i = 0; i < 4; i++) {
        v[i] = src[tid + i * 128];
        s += v[i];
        s2 += v[i] * v[i];
    }
    __shared__ float rs[128], rs2[128];
    rs[tid] = s; rs2[tid] = s2;
    __syncthreads();
    for (int o = 64; o > 0; o >>= 1) {
        if (tid < o) { rs[tid] += rs[tid + o]; rs2[tid] += rs2[tid + o]; }
        __syncthreads();
    }
    float mean = rs[0] * (1.f / 512.f);
    float var  = rs2[0] * (1.f / 512.f) - mean * mean;
    float rstd = rsqrtf(var + 1e-5f);
    #pragma unroll
    for (int i = 0; i < 4; i++) {
        int c = tid + i * 128;
        dst[c] = __float2half((v[i] - mean) * rstd * gamma[c] + beta[c]);
    }
}

// ---------------- RoPE + Q/K assembly -> fp16 (REFERENCE semantics) ---------
__global__ void rope_assemble_kernel(const float* __restrict__ q,
                                     const float* __restrict__ kv,
                                     const float* __restrict__ knope,
                                     const float* __restrict__ cosT,
                                     const float* __restrict__ sinT,
                                     __half* __restrict__ Qh,
                                     __half* __restrict__ Kh)
{
    int idx = blockIdx.x * blockDim.x + threadIdx.x;
    if (idx >= ROWS * HH * 32) return;
    int p   = idx & 31;
    int h   = (idx >> 5) & 15;
    int row = idx >> 9;
    int s   = row & (SS - 1);
    const float scale = 0.07216878364870322f;   // 192^-0.5

    float cv = cosT[s * 32 + p];
    float sv = sinT[s * 32 + p];

    size_t qko = ((size_t)row * HH + h) * QKHD;

    // ---- Q: nope copy (scaled) + rope pair (scaled) ----
    {
        size_t qb = (size_t)row * QCOLS + h * QKHD;
        float4 nv = *(const float4*)&q[qb + p * 4];
        *(__half2*)&Qh[qko + p * 4]     = __floats2half2_rn(nv.x * scale, nv.y * scale);
        *(__half2*)&Qh[qko + p * 4 + 2] = __floats2half2_rn(nv.z * scale, nv.w * scale);
        float a = q[qb + NOPE + 2 * p], b = q[qb + NOPE + 2 * p + 1];
        *(__half2*)&Qh[qko + NOPE + 2 * p] =
            __floats2half2_rn((a * cv - b * sv) * scale, (a * sv + b * cv) * scale);
    }

    // ---- K: concat-reshape gather + rope ----
    const float* knr = knope + (size_t)row * (HH * NOPE);
    const float* krr = kv + (size_t)row * KVCOLS;
    {
        int gg = h * QKHD + p * 4;
        float4 nv;
        if (gg < HH * NOPE) nv = *(const float4*)&knr[gg];
        else                nv = *(const float4*)&krr[gg - HH * NOPE];
        *(__half2*)&Kh[qko + p * 4]     = __floats2half2_rn(nv.x, nv.y);
        *(__half2*)&Kh[qko + p * 4 + 2] = __floats2half2_rn(nv.z, nv.w);
    }
    {
        int gg = h * QKHD + NOPE + 2 * p;
        float ka, kb;
        if (gg < HH * NOPE) { ka = knr[gg];              kb = knr[gg + 1]; }
        else                { ka = krr[gg - HH * NOPE];  kb = krr[gg - HH * NOPE + 1]; }
        *(__half2*)&Kh[qko + NOPE + 2 * p] =
            __floats2half2_rn(ka * cv - kb * sv, ka * sv + kb * cv);
    }
}

// ---------------- fp16 tensor-core causal flash attention -------------------
// All inputs fp16 in global. BQ=64, BKT=64, 256 threads (wq 0..3 x kh 0..1).
#define ABQ 64
#define ABK 64
#define QSPh 200      // halves per Q/K row
#define VTP  72
#define PSPh 72
#define OSP  132
#define SM_Q 0
#define SM_K (ABQ * QSPh)
#define SM_VT (SM_K + ABK * QSPh)
#define SM_P (SM_VT + 128 * VTP)
#define ATTN_HALVES (SM_P + ABQ * PSPh)
#define ATTN_SMEM (ATTN_HALVES * sizeof(__half))

__global__ __launch_bounds__(256, 2)
void attn_f16_kernel(const __half* __restrict__ Q,
                     const __half* __restrict__ Kf,
                     const __half* __restrict__ V,
                     __half* __restrict__ O)
{
    const int q0 = blockIdx.x * ABQ;
    const int h  = blockIdx.y;
    const int b  = blockIdx.z;

    extern __shared__ __half smh[];
    __half* Qs  = smh + SM_Q;
    __half* Ks  = smh + SM_K;
    __half* Vst = smh + SM_VT;
    __half* Ps  = smh + SM_P;

    const int tid  = threadIdx.x;
    const int lane = tid & 31;
    const int wid  = tid >> 5;
    const int g    = lane >> 2;
    const int tg   = lane & 3;
    const int wq   = wid & 3;
    const int kh   = wid >> 2;
    const int rA   = wq * 16 + g;

    // ---- stage Q (fp16, pre-scaled): 1536 x 16B chunks, 6/thread ----
    const __half* Qg = Q + (((size_t)(b * SS + q0)) * HH + h) * QKHD;
    #pragma unroll
    for (int n = 0; n < 6; n++) {
        int i = tid + n * 256;
        int r = i / 24, c = (i % 24) * 8;
        *(uint4*)&Qs[r * QSPh + c] = *(const uint4*)&Qg[(size_t)r * (HH * QKHD) + c];
    }

    float m0 = -INFINITY, m1 = -INFINITY, l0 = 0.f, l1 = 0.f;
    float acc[16][4];
    #pragma unroll
    for (int nt = 0; nt < 16; nt++)
        #pragma unroll
        for (int i = 0; i < 4; i++) acc[nt][i] = 0.f;

    const int jend = blockIdx.x;
    for (int j = 0; j <= jend; j++) {
        const int k0 = j * ABK;
        __syncthreads();
        // ---- stage K (fp16 copy): 1536 chunks ----
        const __half* Kg = Kf + (((size_t)(b * SS + k0)) * HH + h) * QKHD;
        #pragma unroll
        for (int n = 0; n < 6; n++) {
            int i = tid + n * 256;
            int r = i / 24, c = (i % 24) * 8;
            *(uint4*)&Ks[r * QSPh + c] = *(const uint4*)&Kg[(size_t)r * (HH * QKHD) + c];
        }
        // ---- stage V transposed: Vst[d][kv] ----
        const __half* Vg = V + (((size_t)(b * SS + k0)) * HH + h) * VHD;
        #pragma unroll
        for (int n = 0; n < 4; n++) {
            int i = tid + n * 256;
            int d4 = i >> 5, kv = (i & 31) * 2;
            uint2 u0 = *(const uint2*)&Vg[(size_t)kv * (HH * VHD) + d4 * 4];
            uint2 u1 = *(const uint2*)&Vg[(size_t)(kv + 1) * (HH * VHD) + d4 * 4];
            const __half* h0 = (const __half*)&u0;
            const __half* h1 = (const __half*)&u1;
            #pragma unroll
            for (int jj = 0; jj < 4; jj++) {
                __half2 pr;
                pr.x = h0[jj]; pr.y = h1[jj];
                *(__half2*)&Vst[(d4 * 4 + jj) * VTP + kv] = pr;
            }
        }
        __syncthreads();

        // ---- QK^T: 16x32 per warp, f16 mma (12 k-steps) ----
        float sc[4][4];
        #pragma unroll
        for (int nt = 0; nt < 4; nt++)
            #pragma unroll
            for (int i = 0; i < 4; i++) sc[nt][i] = 0.f;

        #pragma unroll
        for (int kc = 0; kc < 12; kc++) {
            const int kk = kc * 16 + 2 * tg;
            uint32_t af[4];
            af[0] = *(const uint32_t*)&Qs[rA * QSPh + kk];
            af[1] = *(const uint32_t*)&Qs[(rA + 8) * QSPh + kk];
            af[2] = *(const uint32_t*)&Qs[rA * QSPh + kk + 8];
            af[3] = *(const uint32_t*)&Qs[(rA + 8) * QSPh + kk + 8];
            #pragma unroll
            for (int nt = 0; nt < 4; nt++) {
                int kvr = kh * 32 + nt * 8 + g;
                uint32_t bf[2];
                bf[0] = *(const uint32_t*)&Ks[kvr * QSPh + kk];
                bf[1] = *(const uint32_t*)&Ks[kvr * QSPh + kk + 8];
                mma_f16(sc[nt], af, bf);
            }
        }

        // ---- causal mask ----
        if (j == jend) {
            #pragma unroll
            for (int nt = 0; nt < 4; nt++) {
                int colb = k0 + kh * 32 + nt * 8 + 2 * tg;
                int row0g = q0 + rA, row1g = q0 + rA + 8;
                if (colb     > row0g) sc[nt][0] = -INFINITY;
                if (colb + 1 > row0g) sc[nt][1] = -INFINITY;
                if (colb     > row1g) sc[nt][2] = -INFINITY;
                if (colb + 1 > row1g) sc[nt][3] = -INFINITY;
            }
        }

        // ---- online softmax ----
        float ml0 = -INFINITY, ml1 = -INFINITY;
        #pragma unroll
        for (int nt = 0; nt < 4; nt++) {
            ml0 = fmaxf(ml0, fmaxf(sc[nt][0], sc[nt][1]));
            ml1 = fmaxf(ml1, fmaxf(sc[nt][2], sc[nt][3]));
        }
        ml0 = fmaxf(ml0, __shfl_xor_sync(0xffffffffu, ml0, 1));
        ml0 = fmaxf(ml0, __shfl_xor_sync(0xffffffffu, ml0, 2));
        ml1 = fmaxf(ml1, __shfl_xor_sync(0xffffffffu, ml1, 1));
        ml1 = fmaxf(ml1, __shfl_xor_sync(0xffffffffu, ml1, 2));
        float mn0 = fmaxf(m0, ml0), mn1 = fmaxf(m1, ml1);
        float mr0 = (mn0 == -INFINITY) ? 0.f : mn0;
        float mr1 = (mn1 == -INFINITY) ? 0.f : mn1;
        float a0 = __expf(m0 - mr0);
        float a1 = __expf(m1 - mr1);

        float ll0 = 0.f, ll1 = 0.f;
        #pragma unroll
        for (int nt = 0; nt < 4; nt++) {
            __half2 h0 = __floats2half2_rn(__expf(sc[nt][0] - mr0), __expf(sc[nt][1] - mr0));
            __half2 h1 = __floats2half2_rn(__expf(sc[nt][2] - mr1), __expf(sc[nt][3] - mr1));
            int cb = kh * 32 + nt * 8 + 2 * tg;
            *(__half2*)&Ps[rA * PSPh + cb]       = h0;
            *(__half2*)&Ps[(rA + 8) * PSPh + cb] = h1;
            float2 f0 = __half22float2(h0);
            float2 f1 = __half22float2(h1);
            ll0 += f0.x + f0.y;
            ll1 += f1.x + f1.y;
        }
        ll0 += __shfl_xor_sync(0xffffffffu, ll0, 1);
        ll0 += __shfl_xor_sync(0xffffffffu, ll0, 2);
        ll1 += __shfl_xor_sync(0xffffffffu, ll1, 1);
        ll1 += __shfl_xor_sync(0xffffffffu, ll1, 2);

        m0 = mn0; m1 = mn1;
        l0 = l0 * a0 + ll0;
        l1 = l1 * a1 + ll1;

        #pragma unroll
        for (int nt = 0; nt < 16; nt++) {
            acc[nt][0] *= a0; acc[nt][1] *= a0;
            acc[nt][2] *= a1; acc[nt][3] *= a1;
        }
        __syncwarp();

        // ---- PV: f16 mma over transposed V (2 k-steps) ----
        #pragma unroll
        for (int kc = 0; kc < 2; kc++) {
            const int kk = kh * 32 + kc * 16 + 2 * tg;
            uint32_t af[4];
            af[0] = *(const uint32_t*)&Ps[rA * PSPh + kk];
            af[1] = *(const uint32_t*)&Ps[(rA + 8) * PSPh + kk];
            af[2] = *(const uint32_t*)&Ps[rA * PSPh + kk + 8];
            af[3] = *(const uint32_t*)&Ps[(rA + 8) * PSPh + kk + 8];
            #pragma unroll
            for (int nt = 0; nt < 16; nt++) {
                int d = nt * 8 + g;
                uint32_t bf[2];
                bf[0] = *(const uint32_t*)&Vst[d * VTP + kk];
                bf[1] = *(const uint32_t*)&Vst[d * VTP + kk + 8];
                mma_f16(acc[nt], af, bf);
            }
        }
        __syncwarp();
    }

    // ---- merge kv halves; write fp16 O ----
    __syncthreads();
    float* Osh = (float*)(smh + SM_K);
    float* msh = (float*)(smh + SM_P);
    float* lsh = msh + 64;

    if (kh == 1) {
        if (tg == 0) {
            msh[rA] = m0;  msh[rA + 8] = m1;
            lsh[rA] = l0;  lsh[rA + 8] = l1;
        }
        #pragma unroll
        for (int nt = 0; nt < 16; nt++) {
            int cb = nt * 8 + 2 * tg;
            *(float2*)&Osh[rA * OSP + cb]       = make_float2(acc[nt][0], acc[nt][1]);
            *(float2*)&Osh[(rA + 8) * OSP + cb] = make_float2(acc[nt][2], acc[nt][3]);
        }
    }
    __syncthreads();
    if (kh == 0) {
        float mB0 = msh[rA], mB1 = msh[rA + 8];
        float lB0 = lsh[rA], lB1 = lsh[rA + 8];
        float mm0 = fmaxf(m0, mB0), mm1 = fmaxf(m1, mB1);
        float wA0 = __expf(m0 - mm0),  wB0 = __expf(mB0 - mm0);
        float wA1 = __expf(m1 - mm1),  wB1 = __expf(mB1 - mm1);
        float inv0 = 1.f / (wA0 * l0 + wB0 * lB0);
        float inv1 = 1.f / (wA1 * l1 + wB1 * lB1);

        size_t ob0 = (((size_t)(b * SS + q0 + rA)) * HH + h) * VHD;
        size_t ob1 = (((size_t)(b * SS + q0 + rA + 8)) * HH + h) * VHD;
        #pragma unroll
        for (int nt = 0; nt < 16; nt++) {
            int cb = nt * 8 + 2 * tg;
            float2 oB0 = *(float2*)&Osh[rA * OSP + cb];
            float2 oB1 = *(float2*)&Osh[(rA + 8) * OSP + cb];
            __half2 h0 = __floats2half2_rn((wA0 * acc[nt][0] + wB0 * oB0.x) * inv0,
                                           (wA0 * acc[nt][1] + wB0 * oB0.y) * inv0);
            __half2 h1 = __floats2half2_rn((wA1 * acc[nt][2] + wB1 * oB1.x) * inv1,
                                           (wA1 * acc[nt][3] + wB1 * oB1.y) * inv1);
            *(__half2*)&O[ob0 + cb] = h0;
            *(__half2*)&O[ob1 + cb] = h1;
        }
    }
}

// ---------------- launch -----------------------------------------------------
extern "C" void kernel_launch(void* const* d_in, const int* in_sizes, int n_in,
                              void* d_out, int out_size)
{
    const float* x       = (const float*)d_in[0];
    const float* wq_w    = (const float*)d_in[1];
    const float* wq_b    = (const float*)d_in[2];
    const float* wkv_a_w = (const float*)d_in[3];
    const float* wkv_a_b = (const float*)d_in[4];
    const float* kvn_g   = (const float*)d_in[5];
    const float* kvn_b   = (const float*)d_in[6];
    const float* wk_w    = (const float*)d_in[7];
    const float* wk_b    = (const float*)d_in[8];
    const float* wv_w    = (const float*)d_in[9];
    const float* wv_b    = (const float*)d_in[10];
    const float* wo_w    = (const float*)d_in[11];
    const float* wo_b    = (const float*)d_in[12];
    const float* cosT    = (const float*)d_in[13];
    const float* sinT    = (const float*)d_in[14];
    float* out = (float*)d_out;

    float *gq, *gkv, *gkn;
    __half *gc, *gvh, *gQh, *gKh, *gO, *xt, *wqt, *wkvt, *wkt, *wvt, *wot;
    cudaGetSymbolAddress((void**)&gq,   g_q);
    cudaGetSymbolAddress((void**)&gkv,  g_kv);
    cudaGetSymbolAddress((void**)&gc,   g_c);
    cudaGetSymbolAddress((void**)&gkn,  g_kn);
    cudaGetSymbolAddress((void**)&gvh,  g_vh);
    cudaGetSymbolAddress((void**)&gQh,  g_Qh);
    cudaGetSymbolAddress((void**)&gKh,  g_Kh);
    cudaGetSymbolAddress((void**)&gO,   g_O);
    cudaGetSymbolAddress((void**)&xt,   g_xt);
    cudaGetSymbolAddress((void**)&wqt,  g_wqt);
    cudaGetSymbolAddress((void**)&wkvt, g_wkvt);
    cudaGetSymbolAddress((void**)&wkt,  g_wkt);
    cudaGetSymbolAddress((void**)&wvt,  g_wvt);
    cudaGetSymbolAddress((void**)&wot,  g_wot);

    cudaFuncSetAttribute(gemm_f16_kernel, cudaFuncAttributeMaxDynamicSharedMemorySize, (int)GEMM_SMEM);
    cudaFuncSetAttribute(gemm_f16_hout_kernel, cudaFuncAttributeMaxDynamicSharedMemorySize, (int)GEMM_SMEM);
    cudaFuncSetAttribute(attn_f16_kernel, cudaFuncAttributeMaxDynamicSharedMemorySize, (int)ATTN_SMEM);

    // 0a) x -> fp16
    {
        int n4 = ROWS * DIM / 4;
        f2h_kernel<<<(n4 + 255) / 256, 256>>>(x, xt, n4);
    }
    // 0b) transpose+round weights
    transpose_w_kernel<<<dim3(QCOLS/32,  DIM/32),    256>>>(wq_w,    wqt,  DIM,    QCOLS);
    transpose_w_kernel<<<dim3(KVCOLS/32, DIM/32),    256>>>(wkv_a_w, wkvt, DIM,    KVCOLS);
    transpose_w_kernel<<<dim3((HH*NOPE)/32, KVRANK/32), 256>>>(wk_w, wkt,  KVRANK, HH*NOPE);
    transpose_w_kernel<<<dim3((HH*VHD)/32,  KVRANK/32), 256>>>(wv_w, wvt,  KVRANK, HH*VHD);
    transpose_w_kernel<<<dim3(DIM/32, (HH*VHD)/32),  256>>>(wo_w,    wot,  HH*VHD, DIM);

    // 1) q = x @ wq_w + b (fp32 out, rope needs it)
    gemm_f16_kernel<<<dim3(QCOLS/GBN, ROWS/GBM), 256, GEMM_SMEM>>>(wqt, xt, wq_b, gq, ROWS, QCOLS, DIM);
    // 2) kv = x @ wkv_a_w + b
    gemm_f16_kernel<<<dim3(KVCOLS/GBN, ROWS/GBM), 256, GEMM_SMEM>>>(wkvt, xt, wkv_a_b, gkv, ROWS, KVCOLS, DIM);
    // 3) layernorm (fp16 output)
    ln_kernel<<<ROWS, 128>>>(gkv, kvn_g, kvn_b, gc);
    // 4) k_nope = c @ wk_w + b (fp32, rope gathers it)
    gemm_f16_kernel<<<dim3((HH*NOPE)/GBN, ROWS/GBM), 256, GEMM_SMEM>>>(wkt, gc, wk_b, gkn, ROWS, HH*NOPE, KVRANK);
    // 5) v = c @ wv_w + b (fp16 output)
    gemm_f16_hout_kernel<<<dim3((HH*VHD)/GBN, ROWS/GBM), 256, GEMM_SMEM>>>(wvt, gc, wv_b, gvh, ROWS, HH*VHD, KVRANK);
    // 6) rope + assemble -> fp16 Qh (pre-scaled) and Kh
    {
        int total = ROWS * HH * 32;
        rope_assemble_kernel<<<(total + 255) / 256, 256>>>(gq, gkv, gkn, cosT, sinT, gQh, gKh);
    }
    // 7) attention (all-fp16 inputs)
    attn_f16_kernel<<<dim3(SS/ABQ, HH, BB), 256, ATTN_SMEM>>>(gQh, gKh, gvh, gO);
    // 8) out = O @ wo_w + b
    gemm_f16_kernel<<<dim3(DIM/GBN, ROWS/GBM), 256, GEMM_SMEM>>>(wot, gO, wo_b, out, ROWS, DIM, HH*VHD);
}

// round 17
// speedup vs baseline: 1.6402x; 1.0582x over previous
#include <cuda_runtime.h>
#include <cuda_fp16.h>
#include <cuda_bf16.h>
#include <math.h>
#include <stdint.h>

// ---------------- problem constants ----------------
#define BB    2
#define SS    2048
#define DIM   2048
#define HH    16
#define NOPE  128
#define ROPE  64
#define QKHD  192
#define VHD   128
#define KVRANK 512
#define ROWS  (BB*SS)             // 4096
#define QCOLS (HH*QKHD)           // 3072
#define KVCOLS (KVRANK + HH*ROPE) // 1536

// ---------------- scratch (device globals) ----------------------------------
__device__ __half g_qh [ROWS * QCOLS];      // q proj (fp16, pre-rope)
__device__ float  g_kv [ROWS * KVCOLS];
__device__ __half g_c  [ROWS * KVRANK];
__device__ __half g_knh[ROWS * HH * NOPE];  // k_nope fp16
__device__ __half g_vh [ROWS * HH * VHD];   // fp16 V
__device__ __half g_Qh [ROWS * HH * QKHD];  // fp16 Q, rope'd + pre-scaled
__device__ __half g_Kh [ROWS * HH * QKHD];  // fp16 K, assembled + rope'd
__device__ __half g_O  [ROWS * HH * VHD];
__device__ __half g_xt   [ROWS * DIM];
__device__ __half g_wqt  [QCOLS * DIM];
__device__ __half g_wkvt [KVCOLS * DIM];
__device__ __half g_wkt  [HH * NOPE * KVRANK];
__device__ __half g_wvt  [HH * VHD * KVRANK];
__device__ __half g_wot  [DIM * HH * VHD];

// ---------------- helpers -----------------------------------------------------
__device__ __forceinline__ void mma_f16(float* d, const uint32_t* a, const uint32_t* b) {
    asm volatile(
        "mma.sync.aligned.m16n8k16.row.col.f32.f16.f16.f32 "
        "{%0,%1,%2,%3}, {%4,%5,%6,%7}, {%8,%9}, {%0,%1,%2,%3};"
        : "+f"(d[0]), "+f"(d[1]), "+f"(d[2]), "+f"(d[3])
        : "r"(a[0]), "r"(a[1]), "r"(a[2]), "r"(a[3]), "r"(b[0]), "r"(b[1]));
}

// ---------------- prep: fp32 -> fp16 (plain layout, activations) ------------
__global__ void f2h_kernel(const float* __restrict__ src,
                           __half* __restrict__ dst, int n4)
{
    int i = blockIdx.x * blockDim.x + threadIdx.x;
    if (i >= n4) return;
    float4 v = *(const float4*)&src[i * 4];
    *(__half2*)&dst[i * 4]     = __floats2half2_rn(v.x, v.y);
    *(__half2*)&dst[i * 4 + 2] = __floats2half2_rn(v.z, v.w);
}

// ---------------- prep: transpose+round weights (W[K][N] -> Wt[N][K] fp16) --
__global__ void transpose_w_kernel(const float* __restrict__ W,
                                   __half* __restrict__ Wt, int K, int N)
{
    __shared__ float t[32][33];
    const int kb0 = blockIdx.y * 32;
    const int nb0 = blockIdx.x * 32;
    const int tid = threadIdx.x;   // 256
    #pragma unroll
    for (int it = 0; it < 4; it++) {
        int kl = (tid >> 5) + it * 8;
        int nl = tid & 31;
        t[kl][nl] = W[(size_t)(kb0 + kl) * N + nb0 + nl];
    }
    __syncthreads();
    #pragma unroll
    for (int it = 0; it < 4; it++) {
        int nl = (tid >> 5) + it * 8;
        int kl = tid & 31;
        Wt[(size_t)(nb0 + nl) * K + kb0 + kl] = __float2half(t[kl][nl]);
    }
}

// ---------------- fp16 tensor-core GEMM (fp32 output) -----------------------
#define GBM 128
#define GBN 128
#define GBK 32
#define TPAD 40
#define TILE_STAGE (128 * TPAD)
#define GEMM_SMEM ((4 * TILE_STAGE) * sizeof(__half))

#define STAGE_LOAD(s_, kt_) do {                                               \
    _Pragma("unroll")                                                          \
    for (int n_ = 0; n_ < 2; n_++) {                                           \
        int i_ = tid + n_ * 256; int r_ = i_ >> 2; int c_ = (i_ & 3) * 8;      \
        uint32_t da_ = as_base + (uint32_t)(((s_) * TILE_STAGE + r_ * TPAD + c_) * 2); \
        asm volatile("cp.async.cg.shared.global [%0], [%1], 16;"               \
                     :: "r"(da_), "l"(Act + (size_t)(row0 + r_) * K + (kt_) * GBK + c_)); \
        uint32_t dw_ = ws_base + (uint32_t)(((s_) * TILE_STAGE + r_ * TPAD + c_) * 2); \
        asm volatile("cp.async.cg.shared.global [%0], [%1], 16;"               \
                     :: "r"(dw_), "l"(Wt + (size_t)(col0 + r_) * K + (kt_) * GBK + c_)); \
    }                                                                          \
    asm volatile("cp.async.commit_group;");                                    \
} while (0)

__global__ __launch_bounds__(256, 2)
void gemm_f16_kernel(const __half* __restrict__ Wt, const __half* __restrict__ Act,
                     const float* __restrict__ bias, float* __restrict__ C,
                     int M, int N, int K)
{
    extern __shared__ __half sh[];
    __half* As = sh;
    __half* Ws = sh + 2 * TILE_STAGE;

    const int tid  = threadIdx.x;
    const int lane = tid & 31;
    const int warp = tid >> 5;
    const int g  = lane >> 2;
    const int tg = lane & 3;
    const int wm = warp & 3;
    const int wn = warp >> 2;
    const int row0 = blockIdx.y * GBM;
    const int col0 = blockIdx.x * GBN;

    const uint32_t as_base = (uint32_t)__cvta_generic_to_shared(As);
    const uint32_t ws_base = (uint32_t)__cvta_generic_to_shared(Ws);

    float acc[2][8][4];
    #pragma unroll
    for (int mt = 0; mt < 2; mt++)
        #pragma unroll
        for (int nt = 0; nt < 8; nt++)
            #pragma unroll
            for (int i = 0; i < 4; i++) acc[mt][nt][i] = 0.f;

    const int KT = K / GBK;
    STAGE_LOAD(0, 0);

    for (int kt = 0; kt < KT; kt++) {
        const int s = kt & 1;
        if (kt + 1 < KT) {
            STAGE_LOAD(1 - s, kt + 1);
            asm volatile("cp.async.wait_group 1;");
        } else {
            asm volatile("cp.async.wait_group 0;");
        }
        __syncthreads();

        const __half* Asl = As + s * TILE_STAGE;
        const __half* Wsl = Ws + s * TILE_STAGE;

        #pragma unroll
        for (int ks = 0; ks < 2; ks++) {
            const int kk = ks * 16 + 2 * tg;
            uint32_t af[2][4];
            #pragma unroll
            for (int mt = 0; mt < 2; mt++) {
                int row = wm * 32 + mt * 16 + g;
                af[mt][0] = *(const uint32_t*)&Asl[row * TPAD + kk];
                af[mt][1] = *(const uint32_t*)&Asl[(row + 8) * TPAD + kk];
                af[mt][2] = *(const uint32_t*)&Asl[row * TPAD + kk + 8];
                af[mt][3] = *(const uint32_t*)&Asl[(row + 8) * TPAD + kk + 8];
            }
            #pragma unroll
            for (int nt = 0; nt < 8; nt++) {
                int col = wn * 64 + nt * 8 + g;
                uint32_t bf[2];
                bf[0] = *(const uint32_t*)&Wsl[col * TPAD + kk];
                bf[1] = *(const uint32_t*)&Wsl[col * TPAD + kk + 8];
                #pragma unroll
                for (int mt = 0; mt < 2; mt++)
                    mma_f16(acc[mt][nt], af[mt], bf);
            }
        }
        __syncthreads();
    }

    #pragma unroll
    for (int mt = 0; mt < 2; mt++) {
        int r = row0 + wm * 32 + mt * 16 + g;
        #pragma unroll
        for (int nt = 0; nt < 8; nt++) {
            int c = col0 + wn * 64 + nt * 8 + tg * 2;
            float b0 = bias[c], b1 = bias[c + 1];
            float2 v0 = make_float2(acc[mt][nt][0] + b0, acc[mt][nt][1] + b1);
            float2 v1 = make_float2(acc[mt][nt][2] + b0, acc[mt][nt][3] + b1);
            *(float2*)&C[(size_t)r * N + c]       = v0;
            *(float2*)&C[(size_t)(r + 8) * N + c] = v1;
        }
    }
}

// ---------------- fp16 tensor-core GEMM (fp16 output) -----------------------
__global__ __launch_bounds__(256, 2)
void gemm_f16_hout_kernel(const __half* __restrict__ Wt, const __half* __restrict__ Act,
                          const float* __restrict__ bias, __half* __restrict__ C,
                          int M, int N, int K)
{
    extern __shared__ __half sh[];
    __half* As = sh;
    __half* Ws = sh + 2 * TILE_STAGE;

    const int tid  = threadIdx.x;
    const int lane = tid & 31;
    const int warp = tid >> 5;
    const int g  = lane >> 2;
    const int tg = lane & 3;
    const int wm = warp & 3;
    const int wn = warp >> 2;
    const int row0 = blockIdx.y * GBM;
    const int col0 = blockIdx.x * GBN;

    const uint32_t as_base = (uint32_t)__cvta_generic_to_shared(As);
    const uint32_t ws_base = (uint32_t)__cvta_generic_to_shared(Ws);

    float acc[2][8][4];
    #pragma unroll
    for (int mt = 0; mt < 2; mt++)
        #pragma unroll
        for (int nt = 0; nt < 8; nt++)
            #pragma unroll
            for (int i = 0; i < 4; i++) acc[mt][nt][i] = 0.f;

    const int KT = K / GBK;
    STAGE_LOAD(0, 0);

    for (int kt = 0; kt < KT; kt++) {
        const int s = kt & 1;
        if (kt + 1 < KT) {
            STAGE_LOAD(1 - s, kt + 1);
            asm volatile("cp.async.wait_group 1;");
        } else {
            asm volatile("cp.async.wait_group 0;");
        }
        __syncthreads();

        const __half* Asl = As + s * TILE_STAGE;
        const __half* Wsl = Ws + s * TILE_STAGE;

        #pragma unroll
        for (int ks = 0; ks < 2; ks++) {
            const int kk = ks * 16 + 2 * tg;
            uint32_t af[2][4];
            #pragma unroll
            for (int mt = 0; mt < 2; mt++) {
                int row = wm * 32 + mt * 16 + g;
                af[mt][0] = *(const uint32_t*)&Asl[row * TPAD + kk];
                af[mt][1] = *(const uint32_t*)&Asl[(row + 8) * TPAD + kk];
                af[mt][2] = *(const uint32_t*)&Asl[row * TPAD + kk + 8];
                af[mt][3] = *(const uint32_t*)&Asl[(row + 8) * TPAD + kk + 8];
            }
            #pragma unroll
            for (int nt = 0; nt < 8; nt++) {
                int col = wn * 64 + nt * 8 + g;
                uint32_t bf[2];
                bf[0] = *(const uint32_t*)&Wsl[col * TPAD + kk];
                bf[1] = *(const uint32_t*)&Wsl[col * TPAD + kk + 8];
                #pragma unroll
                for (int mt = 0; mt < 2; mt++)
                    mma_f16(acc[mt][nt], af[mt], bf);
            }
        }
        __syncthreads();
    }

    #pragma unroll
    for (int mt = 0; mt < 2; mt++) {
        int r = row0 + wm * 32 + mt * 16 + g;
        #pragma unroll
        for (int nt = 0; nt < 8; nt++) {
            int c = col0 + wn * 64 + nt * 8 + tg * 2;
            float b0 = bias[c], b1 = bias[c + 1];
            *(__half2*)&C[(size_t)r * N + c] =
                __floats2half2_rn(acc[mt][nt][0] + b0, acc[mt][nt][1] + b1);
            *(__half2*)&C[(size_t)(r + 8) * N + c] =
                __floats2half2_rn(acc[mt][nt][2] + b0, acc[mt][nt][3] + b1);
        }
    }
}
#undef STAGE_LOAD

// ---------------- LayerNorm (fp16 output) -----------------------------------
__global__ void ln_kernel(const float* __restrict__ kv,
                          const float* __restrict__ gamma,
                          const float* __restrict__ beta,
                          __half* __restrict__ out)
{
    const int row = blockIdx.x;
    const float* src = kv + (size_t)row * KVCOLS + HH * ROPE;
    __half* dst = out + (size_t)row * KVRANK;
    const int tid = threadIdx.x;

    float v[4];
    float s = 0.f, s2 = 0.f;
    #pragma unroll
    for (int i = 0; i < 4; i++) {
        v[i] = src[tid + i * 128];
        s += v[i];
        s2 += v[i] * v[i];
    }
    __shared__ float rs[128], rs2[128];
    rs[tid] = s; rs2[tid] = s2;
    __syncthreads();
    for (int o = 64; o > 0; o >>= 1) {
        if (tid < o) { rs[tid] += rs[tid + o]; rs2[tid] += rs2[tid + o]; }
        __syncthreads();
    }
    float mean = rs[0] * (1.f / 512.f);
    float var  = rs2[0] * (1.f / 512.f) - mean * mean;
    float rstd = rsqrtf(var + 1e-5f);
    #pragma unroll
    for (int i = 0; i < 4; i++) {
        int c = tid + i * 128;
        dst[c] = __float2half((v[i] - mean) * rstd * gamma[c] + beta[c]);
    }
}

// ---------------- RoPE + Q/K assembly -> fp16 (REFERENCE semantics) ---------
// q and k_nope arrive fp16; kv (k_rope region) fp32.
__global__ void rope_assemble_kernel(const __half* __restrict__ q,
                                     const float* __restrict__ kv,
                                     const __half* __restrict__ knope,
                                     const float* __restrict__ cosT,
                                     const float* __restrict__ sinT,
                                     __half* __restrict__ Qh,
                                     __half* __restrict__ Kh)
{
    int idx = blockIdx.x * blockDim.x + threadIdx.x;
    if (idx >= ROWS * HH * 32) return;
    int p   = idx & 31;
    int h   = (idx >> 5) & 15;
    int row = idx >> 9;
    int s   = row & (SS - 1);
    const float scale = 0.07216878364870322f;   // 192^-0.5

    float cv = cosT[s * 32 + p];
    float sv = sinT[s * 32 + p];

    size_t qko = ((size_t)row * HH + h) * QKHD;

    // ---- Q: nope copy (scaled) + rope pair (scaled) ----
    {
        size_t qb = (size_t)row * QCOLS + h * QKHD;
        __half2 a01 = *(const __half2*)&q[qb + p * 4];
        __half2 a23 = *(const __half2*)&q[qb + p * 4 + 2];
        float2 f01 = __half22float2(a01);
        float2 f23 = __half22float2(a23);
        *(__half2*)&Qh[qko + p * 4]     = __floats2half2_rn(f01.x * scale, f01.y * scale);
        *(__half2*)&Qh[qko + p * 4 + 2] = __floats2half2_rn(f23.x * scale, f23.y * scale);
        float a = __half2float(q[qb + NOPE + 2 * p]);
        float b = __half2float(q[qb + NOPE + 2 * p + 1]);
        *(__half2*)&Qh[qko + NOPE + 2 * p] =
            __floats2half2_rn((a * cv - b * sv) * scale, (a * sv + b * cv) * scale);
    }

    // ---- K: concat-reshape gather + rope ----
    const __half* knr = knope + (size_t)row * (HH * NOPE);
    const float*  krr = kv + (size_t)row * KVCOLS;
    {
        int gg = h * QKHD + p * 4;
        if (gg < HH * NOPE) {
            *(uint2*)&Kh[qko + p * 4] = *(const uint2*)&knr[gg];   // bit copy
        } else {
            float4 nv = *(const float4*)&krr[gg - HH * NOPE];
            *(__half2*)&Kh[qko + p * 4]     = __floats2half2_rn(nv.x, nv.y);
            *(__half2*)&Kh[qko + p * 4 + 2] = __floats2half2_rn(nv.z, nv.w);
        }
    }
    {
        int gg = h * QKHD + NOPE + 2 * p;
        float ka, kb;
        if (gg < HH * NOPE) {
            ka = __half2float(knr[gg]);
            kb = __half2float(knr[gg + 1]);
        } else {
            ka = krr[gg - HH * NOPE];
            kb = krr[gg - HH * NOPE + 1];
        }
        *(__half2*)&Kh[qko + NOPE + 2 * p] =
            __floats2half2_rn(ka * cv - kb * sv, ka * sv + kb * cv);
    }
}

// ---------------- fp16 tensor-core causal flash attention -------------------
// BQ=128, BKT=64. 512 threads = 16 warps (wq 0..7 x kh 0..1).
#define ABQ 128
#define ABK 64
#define QSPh 200
#define VTP  72
#define PSPh 72
#define OSP  132
#define SM_Q 0
#define SM_K (ABQ * QSPh)                 // 25600
#define SM_VT (SM_K + ABK * QSPh)         // 38400
#define SM_P (SM_VT + 128 * VTP)          // 47616
#define ATTN_HALVES (SM_P + ABQ * PSPh)   // 56832
#define ATTN_SMEM (ATTN_HALVES * sizeof(__half))

__global__ __launch_bounds__(512, 1)
void attn_f16_kernel(const __half* __restrict__ Q,
                     const __half* __restrict__ Kf,
                     const __half* __restrict__ V,
                     __half* __restrict__ O)
{
    const int q0 = blockIdx.x * ABQ;
    const int h  = blockIdx.y;
    const int b  = blockIdx.z;

    extern __shared__ __half smh[];
    __half* Qs  = smh + SM_Q;
    __half* Ks  = smh + SM_K;
    __half* Vst = smh + SM_VT;
    __half* Ps  = smh + SM_P;

    const int tid  = threadIdx.x;
    const int lane = tid & 31;
    const int wid  = tid >> 5;
    const int g    = lane >> 2;
    const int tg   = lane & 3;
    const int wq   = wid & 7;           // q stripe 0..7
    const int kh   = wid >> 3;          // kv half 0..1
    const int rA   = wq * 16 + g;       // rows rA, rA+8 in [0,128)

    // ---- stage Q: 128 rows x 24 chunks = 3072, 6/thread ----
    const __half* Qg = Q + (((size_t)(b * SS + q0)) * HH + h) * QKHD;
    #pragma unroll
    for (int n = 0; n < 6; n++) {
        int i = tid + n * 512;
        int r = i / 24, c = (i % 24) * 8;
        *(uint4*)&Qs[r * QSPh + c] = *(const uint4*)&Qg[(size_t)r * (HH * QKHD) + c];
    }

    float m0 = -INFINITY, m1 = -INFINITY, l0 = 0.f, l1 = 0.f;
    float acc[16][4];
    #pragma unroll
    for (int nt = 0; nt < 16; nt++)
        #pragma unroll
        for (int i = 0; i < 4; i++) acc[nt][i] = 0.f;

    const int jend = 2 * blockIdx.x + 1;
    for (int j = 0; j <= jend; j++) {
        const int k0 = j * ABK;
        __syncthreads();
        // ---- stage K: 64 x 24 = 1536 chunks, 3/thread ----
        const __half* Kg = Kf + (((size_t)(b * SS + k0)) * HH + h) * QKHD;
        #pragma unroll
        for (int n = 0; n < 3; n++) {
            int i = tid + n * 512;
            int r = i / 24, c = (i % 24) * 8;
            *(uint4*)&Ks[r * QSPh + c] = *(const uint4*)&Kg[(size_t)r * (HH * QKHD) + c];
        }
        // ---- stage V transposed: 1024 items, 2/thread ----
        const __half* Vg = V + (((size_t)(b * SS + k0)) * HH + h) * VHD;
        #pragma unroll
        for (int n = 0; n < 2; n++) {
            int i = tid + n * 512;
            int d4 = i >> 5, kv = (i & 31) * 2;
            uint2 u0 = *(const uint2*)&Vg[(size_t)kv * (HH * VHD) + d4 * 4];
            uint2 u1 = *(const uint2*)&Vg[(size_t)(kv + 1) * (HH * VHD) + d4 * 4];
            const __half* h0 = (const __half*)&u0;
            const __half* h1 = (const __half*)&u1;
            #pragma unroll
            for (int jj = 0; jj < 4; jj++) {
                __half2 pr;
                pr.x = h0[jj]; pr.y = h1[jj];
                *(__half2*)&Vst[(d4 * 4 + jj) * VTP + kv] = pr;
            }
        }
        __syncthreads();

        // ---- QK^T: 16x32 per warp, f16 mma (12 k-steps) ----
        float sc[4][4];
        #pragma unroll
        for (int nt = 0; nt < 4; nt++)
            #pragma unroll
            for (int i = 0; i < 4; i++) sc[nt][i] = 0.f;

        #pragma unroll
        for (int kc = 0; kc < 12; kc++) {
            const int kk = kc * 16 + 2 * tg;
            uint32_t af[4];
            af[0] = *(const uint32_t*)&Qs[rA * QSPh + kk];
            af[1] = *(const uint32_t*)&Qs[(rA + 8) * QSPh + kk];
            af[2] = *(const uint32_t*)&Qs[rA * QSPh + kk + 8];
            af[3] = *(const uint32_t*)&Qs[(rA + 8) * QSPh + kk + 8];
            #pragma unroll
            for (int nt = 0; nt < 4; nt++) {
                int kvr = kh * 32 + nt * 8 + g;
                uint32_t bf[2];
                bf[0] = *(const uint32_t*)&Ks[kvr * QSPh + kk];
                bf[1] = *(const uint32_t*)&Ks[kvr * QSPh + kk + 8];
                mma_f16(sc[nt], af, bf);
            }
        }

        // ---- causal mask (last two tiles can be partial) ----
        if (k0 + ABK - 1 > q0) {
            #pragma unroll
            for (int nt = 0; nt < 4; nt++) {
                int colb = k0 + kh * 32 + nt * 8 + 2 * tg;
                int row0g = q0 + rA, row1g = q0 + rA + 8;
                if (colb     > row0g) sc[nt][0] = -INFINITY;
                if (colb + 1 > row0g) sc[nt][1] = -INFINITY;
                if (colb     > row1g) sc[nt][2] = -INFINITY;
                if (colb + 1 > row1g) sc[nt][3] = -INFINITY;
            }
        }

        // ---- online softmax ----
        float ml0 = -INFINITY, ml1 = -INFINITY;
        #pragma unroll
        for (int nt = 0; nt < 4; nt++) {
            ml0 = fmaxf(ml0, fmaxf(sc[nt][0], sc[nt][1]));
            ml1 = fmaxf(ml1, fmaxf(sc[nt][2], sc[nt][3]));
        }
        ml0 = fmaxf(ml0, __shfl_xor_sync(0xffffffffu, ml0, 1));
        ml0 = fmaxf(ml0, __shfl_xor_sync(0xffffffffu, ml0, 2));
        ml1 = fmaxf(ml1, __shfl_xor_sync(0xffffffffu, ml1, 1));
        ml1 = fmaxf(ml1, __shfl_xor_sync(0xffffffffu, ml1, 2));
        float mn0 = fmaxf(m0, ml0), mn1 = fmaxf(m1, ml1);
        float mr0 = (mn0 == -INFINITY) ? 0.f : mn0;
        float mr1 = (mn1 == -INFINITY) ? 0.f : mn1;
        float a0 = __expf(m0 - mr0);
        float a1 = __expf(m1 - mr1);

        float ll0 = 0.f, ll1 = 0.f;
        #pragma unroll
        for (int nt = 0; nt < 4; nt++) {
            __half2 h0 = __floats2half2_rn(__expf(sc[nt][0] - mr0), __expf(sc[nt][1] - mr0));
            __half2 h1 = __floats2half2_rn(__expf(sc[nt][2] - mr1), __expf(sc[nt][3] - mr1));
            int cb = kh * 32 + nt * 8 + 2 * tg;
            *(__half2*)&Ps[rA * PSPh + cb]       = h0;
            *(__half2*)&Ps[(rA + 8) * PSPh + cb] = h1;
            float2 f0 = __half22float2(h0);
            float2 f1 = __half22float2(h1);
            ll0 += f0.x + f0.y;
            ll1 += f1.x + f1.y;
        }
        ll0 += __shfl_xor_sync(0xffffffffu, ll0, 1);
        ll0 += __shfl_xor_sync(0xffffffffu, ll0, 2);
        ll1 += __shfl_xor_sync(0xffffffffu, ll1, 1);
        ll1 += __shfl_xor_sync(0xffffffffu, ll1, 2);

        m0 = mn0; m1 = mn1;
        l0 = l0 * a0 + ll0;
        l1 = l1 * a1 + ll1;

        #pragma unroll
        for (int nt = 0; nt < 16; nt++) {
            acc[nt][0] *= a0; acc[nt][1] *= a0;
            acc[nt][2] *= a1; acc[nt][3] *= a1;
        }
        __syncwarp();

        // ---- PV: f16 mma over transposed V (2 k-steps) ----
        #pragma unroll
        for (int kc = 0; kc < 2; kc++) {
            const int kk = kh * 32 + kc * 16 + 2 * tg;
            uint32_t af[4];
            af[0] = *(const uint32_t*)&Ps[rA * PSPh + kk];
            af[1] = *(const uint32_t*)&Ps[(rA + 8) * PSPh + kk];
            af[2] = *(const uint32_t*)&Ps[rA * PSPh + kk + 8];
            af[3] = *(const uint32_t*)&Ps[(rA + 8) * PSPh + kk + 8];
            #pragma unroll
            for (int nt = 0; nt < 16; nt++) {
                int d = nt * 8 + g;
                uint32_t bf[2];
                bf[0] = *(const uint32_t*)&Vst[d * VTP + kk];
                bf[1] = *(const uint32_t*)&Vst[d * VTP + kk + 8];
                mma_f16(acc[nt], af, bf);
            }
        }
        __syncwarp();
    }

    // ---- merge kv halves; write fp16 O ----
    // Osh: 128 rows x OSP floats = 67.6KB, aliases dead Q+K (76.8KB).
    __syncthreads();
    float* Osh = (float*)(smh + SM_Q);
    float* msh = (float*)(smh + SM_P);     // dead P region
    float* lsh = msh + 128;

    if (kh == 1) {
        if (tg == 0) {
            msh[rA] = m0;  msh[rA + 8] = m1;
            lsh[rA] = l0;  lsh[rA + 8] = l1;
        }
        #pragma unroll
        for (int nt = 0; nt < 16; nt++) {
            int cb = nt * 8 + 2 * tg;
            *(float2*)&Osh[rA * OSP + cb]       = make_float2(acc[nt][0], acc[nt][1]);
            *(float2*)&Osh[(rA + 8) * OSP + cb] = make_float2(acc[nt][2], acc[nt][3]);
        }
    }
    __syncthreads();
    if (kh == 0) {
        float mB0 = msh[rA], mB1 = msh[rA + 8];
        float lB0 = lsh[rA], lB1 = lsh[rA + 8];
        float mm0 = fmaxf(m0, mB0), mm1 = fmaxf(m1, mB1);
        float wA0 = __expf(m0 - mm0),  wB0 = __expf(mB0 - mm0);
        float wA1 = __expf(m1 - mm1),  wB1 = __expf(mB1 - mm1);
        float inv0 = 1.f / (wA0 * l0 + wB0 * lB0);
        float inv1 = 1.f / (wA1 * l1 + wB1 * lB1);

        size_t ob0 = (((size_t)(b * SS + q0 + rA)) * HH + h) * VHD;
        size_t ob1 = (((size_t)(b * SS + q0 + rA + 8)) * HH + h) * VHD;
        #pragma unroll
        for (int nt = 0; nt < 16; nt++) {
            int cb = nt * 8 + 2 * tg;
            float2 oB0 = *(float2*)&Osh[rA * OSP + cb];
            float2 oB1 = *(float2*)&Osh[(rA + 8) * OSP + cb];
            __half2 h0 = __floats2half2_rn((wA0 * acc[nt][0] + wB0 * oB0.x) * inv0,
                                           (wA0 * acc[nt][1] + wB0 * oB0.y) * inv0);
            __half2 h1 = __floats2half2_rn((wA1 * acc[nt][2] + wB1 * oB1.x) * inv1,
                                           (wA1 * acc[nt][3] + wB1 * oB1.y) * inv1);
            *(__half2*)&O[ob0 + cb] = h0;
            *(__half2*)&O[ob1 + cb] = h1;
        }
    }
}

// ---------------- launch -----------------------------------------------------
extern "C" void kernel_launch(void* const* d_in, const int* in_sizes, int n_in,
                              void* d_out, int out_size)
{
    const float* x       = (const float*)d_in[0];
    const float* wq_w    = (const float*)d_in[1];
    const float* wq_b    = (const float*)d_in[2];
    const float* wkv_a_w = (const float*)d_in[3];
    const float* wkv_a_b = (const float*)d_in[4];
    const float* kvn_g   = (const float*)d_in[5];
    const float* kvn_b   = (const float*)d_in[6];
    const float* wk_w    = (const float*)d_in[7];
    const float* wk_b    = (const float*)d_in[8];
    const float* wv_w    = (const float*)d_in[9];
    const float* wv_b    = (const float*)d_in[10];
    const float* wo_w    = (const float*)d_in[11];
    const float* wo_b    = (const float*)d_in[12];
    const float* cosT    = (const float*)d_in[13];
    const float* sinT    = (const float*)d_in[14];
    float* out = (float*)d_out;

    float *gkv;
    __half *gqh, *gc, *gknh, *gvh, *gQh, *gKh, *gO, *xt, *wqt, *wkvt, *wkt, *wvt, *wot;
    cudaGetSymbolAddress((void**)&gqh,  g_qh);
    cudaGetSymbolAddress((void**)&gkv,  g_kv);
    cudaGetSymbolAddress((void**)&gc,   g_c);
    cudaGetSymbolAddress((void**)&gknh, g_knh);
    cudaGetSymbolAddress((void**)&gvh,  g_vh);
    cudaGetSymbolAddress((void**)&gQh,  g_Qh);
    cudaGetSymbolAddress((void**)&gKh,  g_Kh);
    cudaGetSymbolAddress((void**)&gO,   g_O);
    cudaGetSymbolAddress((void**)&xt,   g_xt);
    cudaGetSymbolAddress((void**)&wqt,  g_wqt);
    cudaGetSymbolAddress((void**)&wkvt, g_wkvt);
    cudaGetSymbolAddress((void**)&wkt,  g_wkt);
    cudaGetSymbolAddress((void**)&wvt,  g_wvt);
    cudaGetSymbolAddress((void**)&wot,  g_wot);

    cudaFuncSetAttribute(gemm_f16_kernel, cudaFuncAttributeMaxDynamicSharedMemorySize, (int)GEMM_SMEM);
    cudaFuncSetAttribute(gemm_f16_hout_kernel, cudaFuncAttributeMaxDynamicSharedMemorySize, (int)GEMM_SMEM);
    cudaFuncSetAttribute(attn_f16_kernel, cudaFuncAttributeMaxDynamicSharedMemorySize, (int)ATTN_SMEM);

    // 0a) x -> fp16
    {
        int n4 = ROWS * DIM / 4;
        f2h_kernel<<<(n4 + 255) / 256, 256>>>(x, xt, n4);
    }
    // 0b) transpose+round weights
    transpose_w_kernel<<<dim3(QCOLS/32,  DIM/32),    256>>>(wq_w,    wqt,  DIM,    QCOLS);
    transpose_w_kernel<<<dim3(KVCOLS/32, DIM/32),    256>>>(wkv_a_w, wkvt, DIM,    KVCOLS);
    transpose_w_kernel<<<dim3((HH*NOPE)/32, KVRANK/32), 256>>>(wk_w, wkt,  KVRANK, HH*NOPE);
    transpose_w_kernel<<<dim3((HH*VHD)/32,  KVRANK/32), 256>>>(wv_w, wvt,  KVRANK, HH*VHD);
    transpose_w_kernel<<<dim3(DIM/32, (HH*VHD)/32),  256>>>(wo_w,    wot,  HH*VHD, DIM);

    // 1) q = x @ wq_w + b (fp16 out)
    gemm_f16_hout_kernel<<<dim3(QCOLS/GBN, ROWS/GBM), 256, GEMM_SMEM>>>(wqt, xt, wq_b, gqh, ROWS, QCOLS, DIM);
    // 2) kv = x @ wkv_a_w + b (fp32: ln + rope consume)
    gemm_f16_kernel<<<dim3(KVCOLS/GBN, ROWS/GBM), 256, GEMM_SMEM>>>(wkvt, xt, wkv_a_b, gkv, ROWS, KVCOLS, DIM);
    // 3) layernorm (fp16 output)
    ln_kernel<<<ROWS, 128>>>(gkv, kvn_g, kvn_b, gc);
    // 4) k_nope = c @ wk_w + b (fp16 out)
    gemm_f16_hout_kernel<<<dim3((HH*NOPE)/GBN, ROWS/GBM), 256, GEMM_SMEM>>>(wkt, gc, wk_b, gknh, ROWS, HH*NOPE, KVRANK);
    // 5) v = c @ wv_w + b (fp16 output)
    gemm_f16_hout_kernel<<<dim3((HH*VHD)/GBN, ROWS/GBM), 256, GEMM_SMEM>>>(wvt, gc, wv_b, gvh, ROWS, HH*VHD, KVRANK);
    // 6) rope + assemble -> fp16 Qh (pre-scaled) and Kh
    {
        int total = ROWS * HH * 32;
        rope_assemble_kernel<<<(total + 255) / 256, 256>>>(gqh, gkv, gknh, cosT, sinT, gQh, gKh);
    }
    // 7) attention (ABQ=128, all-fp16 inputs)
    attn_f16_kernel<<<dim3(SS/ABQ, HH, BB), 512, ATTN_SMEM>>>(gQh, gKh, gvh, gO);
    // 8) out = O @ wo_w + b
    gemm_f16_kernel<<<dim3(DIM/GBN, ROWS/GBM), 256, GEMM_SMEM>>>(wot, gO, wo_b, out, ROWS, DIM, HH*VHD);
}